// round 2
// baseline (speedup 1.0000x reference)
#include <cuda_runtime.h>
#include <math.h>

#define BATCH 64
#define NMAX  2048
#define NEDGE 32768
#define FIN   256
#define NHID  512
#define RULES 128

// ---------------- scratch (device globals; no allocations) ----------------
static __device__ float g_bufA[(size_t)BATCH * NMAX * NHID];   // 256 MB
static __device__ float g_bufB[(size_t)BATCH * NMAX * NHID];   // 256 MB
static __device__ float g_deg[BATCH * NMAX];
static __device__ float g_s0[BATCH * NMAX];
static __device__ float g_score[BATCH * NMAX];
static __device__ int   g_perm[BATCH * NMAX];
static __device__ int   g_newidx[BATCH * NMAX];
static __device__ int   g_src[BATCH * NEDGE];
static __device__ int   g_dst[BATCH * NEDGE];
static __device__ float g_em[BATCH * NEDGE];
static __device__ float g_z[BATCH * 2 * NHID];

// ---------------- init ----------------
__global__ void k_init_edges(const int* __restrict__ src, const int* __restrict__ dst) {
    int i = blockIdx.x * blockDim.x + threadIdx.x;
    if (i < BATCH * NEDGE) { g_src[i] = src[i]; g_dst[i] = dst[i]; g_em[i] = 1.0f; }
}
__global__ void k_zero_z() {
    int i = blockIdx.x * blockDim.x + threadIdx.x;
    if (i < BATCH * 2 * NHID) g_z[i] = 0.0f;
}

// ---------------- degree ----------------
__global__ void k_deg_init(int n) {
    int i = blockIdx.x * blockDim.x + threadIdx.x;
    if (i < BATCH * n) g_deg[i] = 1.0f;
}
__global__ void k_deg_count(int n) {
    int i = blockIdx.x * blockDim.x + threadIdx.x;
    if (i >= BATCH * NEDGE) return;
    if (g_em[i] != 0.0f) {
        int b = i / NEDGE;
        atomicAdd(&g_deg[b * n + g_dst[i]], 1.0f);
    }
}

// ---------------- fp32 tiled GEMM: C[M,512] = A[M,K] @ W[K,512] ----------------
// BM=128, BN=64, BK=16, 256 threads, 8x4 per thread. M%128==0, K%16==0 assumed.
__global__ void k_gemm(const float* __restrict__ A, const float* __restrict__ W,
                       float* __restrict__ C, int M, int K) {
    __shared__ float As[16][128];
    __shared__ float Bs[16][64];
    const int tid = threadIdx.x;
    const int tx = tid & 15;           // 0..15 -> 4 cols each
    const int ty = tid >> 4;           // 0..15 -> 8 rows each
    const int rowBase = blockIdx.y * 128;
    const int colBase = blockIdx.x * 64;

    float acc[8][4];
#pragma unroll
    for (int i = 0; i < 8; i++)
#pragma unroll
        for (int j = 0; j < 4; j++) acc[i][j] = 0.0f;

    for (int k0 = 0; k0 < K; k0 += 16) {
        // A tile: 128x16 floats = 512 float4, 2 per thread (store transposed)
#pragma unroll
        for (int it = 0; it < 2; it++) {
            int s = tid * 2 + it;      // 0..511
            int r = s >> 2;            // row within tile
            int kc = (s & 3) * 4;      // k within tile
            float4 v = *(const float4*)(A + (size_t)(rowBase + r) * K + k0 + kc);
            As[kc + 0][r] = v.x; As[kc + 1][r] = v.y;
            As[kc + 2][r] = v.z; As[kc + 3][r] = v.w;
        }
        // B tile: 16x64 floats = 256 float4, 1 per thread
        {
            int kr = tid >> 4;         // 0..15
            int c4 = (tid & 15) * 4;
            *(float4*)&Bs[kr][c4] = *(const float4*)(W + (size_t)(k0 + kr) * 512 + colBase + c4);
        }
        __syncthreads();
#pragma unroll
        for (int kk = 0; kk < 16; kk++) {
            float4 a0 = *(float4*)&As[kk][ty * 8];
            float4 a1 = *(float4*)&As[kk][ty * 8 + 4];
            float4 bv = *(float4*)&Bs[kk][tx * 4];
            float av[8] = {a0.x, a0.y, a0.z, a0.w, a1.x, a1.y, a1.z, a1.w};
            float bw[4] = {bv.x, bv.y, bv.z, bv.w};
#pragma unroll
            for (int i = 0; i < 8; i++)
#pragma unroll
                for (int j = 0; j < 4; j++) acc[i][j] = fmaf(av[i], bw[j], acc[i][j]);
        }
        __syncthreads();
    }
#pragma unroll
    for (int i = 0; i < 8; i++) {
        int row = rowBase + ty * 8 + i;
        float4 o = make_float4(acc[i][0], acc[i][1], acc[i][2], acc[i][3]);
        *(float4*)(C + (size_t)row * 512 + colBase + tx * 4) = o;
    }
}

// ---------------- GCN combine: out = h0/deg + bias (self loop + bias) ----------------
__global__ void k_combine(const float* __restrict__ h0, float* __restrict__ out,
                          const float* __restrict__ bias, int n) {
    size_t i = (size_t)blockIdx.x * blockDim.x + threadIdx.x;
    size_t total = (size_t)BATCH * n * NHID;
    if (i >= total) return;
    int row = (int)(i >> 9);
    int f = (int)(i & 511);
    out[i] = h0[i] / g_deg[row] + bias[f];
}

// ---------------- edge scatter (features): warp per edge ----------------
__global__ void k_edge_scatter(const float* __restrict__ h0, float* __restrict__ out, int n) {
    int gw = blockIdx.x * 8 + (threadIdx.x >> 5);   // global warp == edge index
    if (gw >= BATCH * NEDGE) return;
    if (g_em[gw] == 0.0f) return;
    int b = gw / NEDGE;
    int rs = b * n + g_src[gw];
    int rd = b * n + g_dst[gw];
    float coef = rsqrtf(g_deg[rs] * g_deg[rd]);
    int lane = threadIdx.x & 31;
    const float4* hp = (const float4*)(h0 + (size_t)rs * NHID);
    float* op = out + (size_t)rd * NHID;
#pragma unroll
    for (int j = 0; j < 4; j++) {
        int f4 = j * 32 + lane;
        float4 v = hp[f4];
        int base = f4 * 4;
        atomicAdd(op + base + 0, v.x * coef);
        atomicAdd(op + base + 1, v.y * coef);
        atomicAdd(op + base + 2, v.z * coef);
        atomicAdd(op + base + 3, v.w * coef);
    }
}

__global__ void k_relu(float* __restrict__ p, size_t total) {
    size_t i = (size_t)blockIdx.x * blockDim.x + threadIdx.x;
    if (i < total) p[i] = fmaxf(p[i], 0.0f);
}

// ---------------- scorer: s0 = h . Wp ; score = s0/deg + bp ----------------
__global__ void k_scorer(const float* __restrict__ h, const float* __restrict__ Wp,
                         const float* __restrict__ bp, int n) {
    int row = blockIdx.x * 8 + (threadIdx.x >> 5);
    if (row >= BATCH * n) return;
    int lane = threadIdx.x & 31;
    const float* hr = h + (size_t)row * NHID;
    float s = 0.0f;
#pragma unroll
    for (int f = 0; f < NHID; f += 32) s = fmaf(hr[f + lane], Wp[f + lane], s);
#pragma unroll
    for (int o = 16; o > 0; o >>= 1) s += __shfl_down_sync(0xffffffffu, s, o);
    if (lane == 0) {
        g_s0[row] = s;
        g_score[row] = s / g_deg[row] + bp[0];
    }
}

__global__ void k_scorer_scatter(int n) {
    int i = blockIdx.x * blockDim.x + threadIdx.x;
    if (i >= BATCH * NEDGE) return;
    if (g_em[i] == 0.0f) return;
    int b = i / NEDGE;
    int rs = b * n + g_src[i];
    int rd = b * n + g_dst[i];
    float coef = rsqrtf(g_deg[rs] * g_deg[rd]);
    atomicAdd(&g_score[rd], g_s0[rs] * coef);
}

// ---------------- top-k: per-batch bitonic sort in shared memory ----------------
__global__ void k_topk(int n, int k) {
    extern __shared__ char sm[];
    float* sv = (float*)sm;
    int* si = (int*)(sv + n);
    int b = blockIdx.x, tid = threadIdx.x;
    for (int i = tid; i < n; i += blockDim.x) { sv[i] = g_score[b * n + i]; si[i] = i; }
    __syncthreads();
    for (int ksz = 2; ksz <= n; ksz <<= 1) {
        for (int j = ksz >> 1; j > 0; j >>= 1) {
            for (int i = tid; i < n; i += blockDim.x) {
                int ixj = i ^ j;
                if (ixj > i) {
                    float v1 = sv[i], v2 = sv[ixj];
                    int i1 = si[i], i2 = si[ixj];
                    bool before = (v1 > v2) || (v1 == v2 && i1 < i2); // descending, idx-asc tiebreak
                    bool desc = ((i & ksz) == 0);
                    if (desc ? !before : before) {
                        sv[i] = v2; sv[ixj] = v1; si[i] = i2; si[ixj] = i1;
                    }
                }
            }
            __syncthreads();
        }
    }
    for (int i = tid; i < n; i += blockDim.x) g_newidx[b * n + i] = -1;
    __syncthreads();
    for (int t = tid; t < k; t += blockDim.x) {
        int p = si[t];
        g_perm[b * n + t] = p;
        g_newidx[b * n + p] = t;
    }
}

// ---------------- pool apply: out[b,r,:] = h[b,perm[r],:] * tanh(score[perm[r]]) ----------------
__global__ void k_pool(const float* __restrict__ h, float* __restrict__ out, int n, int k) {
    size_t i = (size_t)blockIdx.x * blockDim.x + threadIdx.x;
    size_t total = (size_t)BATCH * k * NHID;
    if (i >= total) return;
    int f = (int)(i & 511);
    int r = (int)((i >> 9) % k);
    int b = (int)(i / ((size_t)k * NHID));
    int p = g_perm[b * n + r];
    float t = tanhf(g_score[b * n + p]);
    out[i] = h[((size_t)b * n + p) * NHID + f] * t;
}

// ---------------- readout: z[b] += concat(max, mean) over k nodes ----------------
__global__ void k_readout(const float* __restrict__ xk, int k) {
    int b = blockIdx.x, f = threadIdx.x;   // 512 threads
    float mx = -INFINITY, sm = 0.0f;
    for (int r = 0; r < k; r++) {
        float v = xk[((size_t)b * k + r) * NHID + f];
        mx = fmaxf(mx, v);
        sm += v;
    }
    g_z[b * 1024 + f] += mx;
    g_z[b * 1024 + 512 + f] += sm / (float)k;
}

// ---------------- edge relabel for next stage ----------------
__global__ void k_edge_update(int n) {
    int i = blockIdx.x * blockDim.x + threadIdx.x;
    if (i >= BATCH * NEDGE) return;
    int b = i / NEDGE;
    if (g_em[i] != 0.0f) {
        int ns = g_newidx[b * n + g_src[i]];
        int nd = g_newidx[b * n + g_dst[i]];
        if (ns >= 0 && nd >= 0) { g_src[i] = ns; g_dst[i] = nd; }
        else { g_em[i] = 0.0f; g_src[i] = 0; g_dst[i] = 0; }
    } else { g_src[i] = 0; g_dst[i] = 0; }
}

// ---------------- head: MLP + log_softmax + value ----------------
__global__ void k_head(const float* __restrict__ l1W, const float* __restrict__ l1b,
                       const float* __restrict__ l2W, const float* __restrict__ l2b,
                       const float* __restrict__ piW, const float* __restrict__ pib,
                       const float* __restrict__ vW, const float* __restrict__ vb,
                       float* __restrict__ out) {
    __shared__ float zz[1024];
    __shared__ float z1[512];
    __shared__ float z2[256];
    __shared__ float lg[128];
    __shared__ float stats[2];
    int b = blockIdx.x, tid = threadIdx.x;   // 256 threads
    for (int i = tid; i < 1024; i += 256) zz[i] = g_z[b * 1024 + i];
    __syncthreads();
    for (int j = tid; j < 512; j += 256) {
        float a = l1b[j];
        for (int i = 0; i < 1024; i++) a = fmaf(zz[i], l1W[i * 512 + j], a);
        z1[j] = fmaxf(a, 0.0f);
    }
    __syncthreads();
    {
        int j = tid;   // 256 outputs
        float a = l2b[j];
        for (int i = 0; i < 512; i++) a = fmaf(z1[i], l2W[i * 256 + j], a);
        z2[j] = fmaxf(a, 0.0f);
    }
    __syncthreads();
    if (tid < 128) {
        float a = pib[tid];
        for (int i = 0; i < 256; i++) a = fmaf(z2[i], piW[i * 128 + tid], a);
        lg[tid] = a;
    } else if (tid == 128) {
        float a = vb[0];
        for (int i = 0; i < 256; i++) a = fmaf(z2[i], vW[i], a);
        out[BATCH * RULES + b] = fmaxf(a, 0.0f);
    }
    __syncthreads();
    if (tid == 0) {
        float mx = -INFINITY;
        for (int i = 0; i < 128; i++) mx = fmaxf(mx, lg[i]);
        float s = 0.0f;
        for (int i = 0; i < 128; i++) s += expf(lg[i] - mx);
        stats[0] = mx;
        stats[1] = logf(s);
    }
    __syncthreads();
    if (tid < 128) out[b * RULES + tid] = lg[tid] - stats[0] - stats[1];
}

// ---------------- host orchestration ----------------
static void run_stage(const float* in, float* h0buf, float* gout, float* poolout,
                      int n, int k, int K,
                      const float* W, const float* bias,
                      const float* Wp, const float* bp, bool relabel) {
    const int EB = BATCH * NEDGE;
    size_t feat_total = (size_t)BATCH * n * NHID;
    k_deg_init<<<(BATCH * n + 255) / 256, 256>>>(n);
    k_deg_count<<<(EB + 255) / 256, 256>>>(n);
    k_gemm<<<dim3(512 / 64, (BATCH * n) / 128), 256>>>(in, W, h0buf, BATCH * n, K);
    k_combine<<<(int)((feat_total + 255) / 256), 256>>>(h0buf, gout, bias, n);
    k_edge_scatter<<<EB / 8, 256>>>(h0buf, gout, n);
    k_relu<<<(int)((feat_total + 255) / 256), 256>>>(gout, feat_total);
    k_scorer<<<(BATCH * n) / 8, 256>>>(gout, Wp, bp, n);
    k_scorer_scatter<<<(EB + 255) / 256, 256>>>(n);
    k_topk<<<BATCH, 1024, n * 8>>>(n, k);
    k_pool<<<(int)(((size_t)BATCH * k * NHID + 255) / 256), 256>>>(gout, poolout, n, k);
    k_readout<<<BATCH, 512>>>(poolout, k);
    if (relabel) k_edge_update<<<(EB + 255) / 256, 256>>>(n);
}

extern "C" void kernel_launch(void* const* d_in, const int* in_sizes, int n_in,
                              void* d_out, int out_size) {
    const float* x    = (const float*)d_in[0];
    const int*   src  = (const int*)d_in[1];
    const int*   dst  = (const int*)d_in[2];
    const float* W1   = (const float*)d_in[3];
    const float* b1   = (const float*)d_in[4];
    const float* Wp1  = (const float*)d_in[5];
    const float* bp1  = (const float*)d_in[6];
    const float* W2   = (const float*)d_in[7];
    const float* b2   = (const float*)d_in[8];
    const float* Wp2  = (const float*)d_in[9];
    const float* bp2  = (const float*)d_in[10];
    const float* W3   = (const float*)d_in[11];
    const float* b3   = (const float*)d_in[12];
    const float* Wp3  = (const float*)d_in[13];
    const float* bp3  = (const float*)d_in[14];
    const float* l1W  = (const float*)d_in[15];
    const float* l1b  = (const float*)d_in[16];
    const float* l2W  = (const float*)d_in[17];
    const float* l2b  = (const float*)d_in[18];
    const float* piW  = (const float*)d_in[19];
    const float* pib  = (const float*)d_in[20];
    const float* vW   = (const float*)d_in[21];
    const float* vb   = (const float*)d_in[22];
    float* out = (float*)d_out;

    float *pA = nullptr, *pB = nullptr;
    cudaGetSymbolAddress((void**)&pA, g_bufA);
    cudaGetSymbolAddress((void**)&pB, g_bufB);

    k_init_edges<<<(BATCH * NEDGE + 255) / 256, 256>>>(src, dst);
    k_zero_z<<<(BATCH * 2 * NHID + 255) / 256, 256>>>();

    // stage 1: x(2048,256) -> h0=A, gcn=B, pool -> A (1024 nodes)
    run_stage(x,  pA, pB, pA, 2048, 1024, FIN,  W1, b1, Wp1, bp1, true);
    // stage 2: A(1024,512) -> h0=B, gcn=A, pool -> B (512 nodes)
    run_stage(pA, pB, pA, pB, 1024, 512,  NHID, W2, b2, Wp2, bp2, true);
    // stage 3: B(512,512) -> h0=A, gcn=B, pool -> A (256 nodes)
    run_stage(pB, pA, pB, pA, 512,  256,  NHID, W3, b3, Wp3, bp3, false);

    k_head<<<BATCH, 256>>>(l1W, l1b, l2W, l2b, piW, pib, vW, vb, out);
}

// round 3
// speedup vs baseline: 2.1915x; 2.1915x over previous
#include <cuda_runtime.h>
#include <math.h>

#define BATCH 64
#define NMAX  2048
#define NEDGE 32768
#define FIN   256
#define NHID  512
#define RULES 128

// ---------------- scratch (device globals; no allocations) ----------------
static __device__ float g_bufA[(size_t)BATCH * NMAX * NHID];   // 256 MB
static __device__ float g_bufB[(size_t)BATCH * NMAX * NHID];   // 256 MB
static __device__ int   g_cnt[BATCH * NMAX];        // in-degree (valid edges)
static __device__ int   g_rowstart[BATCH * NMAX];   // CSR row offsets (per-batch local)
static __device__ int   g_cursor[BATCH * NMAX];
static __device__ int   g_csr[BATCH * NEDGE];       // src local index per CSR slot
static __device__ float g_s0[BATCH * NMAX];
static __device__ float g_score[BATCH * NMAX];
static __device__ int   g_perm[BATCH * NMAX];
static __device__ int   g_newidx[BATCH * NMAX];
static __device__ int   g_src[BATCH * NEDGE];
static __device__ int   g_dst[BATCH * NEDGE];
static __device__ float g_em[BATCH * NEDGE];
static __device__ float g_z[BATCH * 2 * NHID];

// ---------------- init ----------------
__global__ void k_init_edges(const int* __restrict__ src, const int* __restrict__ dst) {
    int i = blockIdx.x * blockDim.x + threadIdx.x;
    if (i < BATCH * NEDGE) { g_src[i] = src[i]; g_dst[i] = dst[i]; g_em[i] = 1.0f; }
}
__global__ void k_zero_z() {
    int i = blockIdx.x * blockDim.x + threadIdx.x;
    if (i < BATCH * 2 * NHID) g_z[i] = 0.0f;
}

// ---------------- CSR build ----------------
__global__ void k_zero_cnt(int n) {
    int i = blockIdx.x * blockDim.x + threadIdx.x;
    if (i < BATCH * n) g_cnt[i] = 0;
}
__global__ void k_count(int n) {
    int i = blockIdx.x * blockDim.x + threadIdx.x;
    if (i >= BATCH * NEDGE) return;
    if (g_em[i] != 0.0f) {
        int b = i / NEDGE;
        atomicAdd(&g_cnt[b * n + g_dst[i]], 1);
    }
}
// per-batch exclusive scan of counts (n is a power of two <= 2048)
__global__ void k_scan(int n) {
    __shared__ int buf[2][NMAX];
    int b = blockIdx.x, tid = threadIdx.x;   // 1024 threads
    for (int i = tid; i < n; i += 1024) buf[0][i] = g_cnt[b * n + i];
    __syncthreads();
    int s = 0;
    for (int d = 1; d < n; d <<= 1) {
        for (int i = tid; i < n; i += 1024) {
            int v = buf[s][i];
            if (i >= d) v += buf[s][i - d];
            buf[s ^ 1][i] = v;
        }
        __syncthreads();
        s ^= 1;
    }
    for (int i = tid; i < n; i += 1024) {
        int excl = (i == 0) ? 0 : buf[s][i - 1];
        g_rowstart[b * n + i] = excl;
        g_cursor[b * n + i] = excl;
    }
}
__global__ void k_fill(int n) {
    int i = blockIdx.x * blockDim.x + threadIdx.x;
    if (i >= BATCH * NEDGE) return;
    if (g_em[i] == 0.0f) return;
    int b = i / NEDGE;
    int pos = atomicAdd(&g_cursor[b * n + g_dst[i]], 1);
    g_csr[b * NEDGE + pos] = g_src[i];
}

// ---------------- fp32 GEMM: C[M,512] = A[M,K] @ W[K,512] ----------------
// 128x128 tile, BK=16, 256 threads, 8x8 microtile, double-buffered smem.
__global__ __launch_bounds__(256) void k_gemm(const float* __restrict__ A,
                                              const float* __restrict__ W,
                                              float* __restrict__ C, int M, int K) {
    __shared__ float As[2][16][128];
    __shared__ float Bs[2][16][128];
    const int tid = threadIdx.x;
    const int tx = tid & 15;
    const int ty = tid >> 4;
    const int rowBase = blockIdx.y * 128;
    const int colBase = blockIdx.x * 128;

    float acc[8][8];
#pragma unroll
    for (int i = 0; i < 8; i++)
#pragma unroll
        for (int j = 0; j < 8; j++) acc[i][j] = 0.0f;

    const int ntiles = K >> 4;
    float4 pa[2], pb[2];

    // preload tile 0
#pragma unroll
    for (int it = 0; it < 2; it++) {
        int sA = tid + it * 256;
        pa[it] = *(const float4*)(A + (size_t)(rowBase + (sA >> 2)) * K + (sA & 3) * 4);
        int sB = tid + it * 256;
        pb[it] = *(const float4*)(W + (size_t)(sB >> 5) * 512 + colBase + (sB & 31) * 4);
    }
#pragma unroll
    for (int it = 0; it < 2; it++) {
        int sA = tid + it * 256;
        int r = sA >> 2, kc = (sA & 3) * 4;
        As[0][kc + 0][r] = pa[it].x; As[0][kc + 1][r] = pa[it].y;
        As[0][kc + 2][r] = pa[it].z; As[0][kc + 3][r] = pa[it].w;
        int sB = tid + it * 256;
        *(float4*)&Bs[0][sB >> 5][(sB & 31) * 4] = pb[it];
    }
    __syncthreads();

    for (int t = 0; t < ntiles; t++) {
        const int cur = t & 1, nxt = cur ^ 1;
        if (t + 1 < ntiles) {
            int k0 = (t + 1) * 16;
#pragma unroll
            for (int it = 0; it < 2; it++) {
                int sA = tid + it * 256;
                pa[it] = *(const float4*)(A + (size_t)(rowBase + (sA >> 2)) * K + k0 + (sA & 3) * 4);
                int sB = tid + it * 256;
                pb[it] = *(const float4*)(W + (size_t)(k0 + (sB >> 5)) * 512 + colBase + (sB & 31) * 4);
            }
        }
#pragma unroll
        for (int kk = 0; kk < 16; kk++) {
            float4 x0 = *(float4*)&As[cur][kk][ty * 4];
            float4 x1 = *(float4*)&As[cur][kk][ty * 4 + 64];
            float4 y0 = *(float4*)&Bs[cur][kk][tx * 4];
            float4 y1 = *(float4*)&Bs[cur][kk][tx * 4 + 64];
            float av[8] = {x0.x, x0.y, x0.z, x0.w, x1.x, x1.y, x1.z, x1.w};
            float bw[8] = {y0.x, y0.y, y0.z, y0.w, y1.x, y1.y, y1.z, y1.w};
#pragma unroll
            for (int i = 0; i < 8; i++)
#pragma unroll
                for (int j = 0; j < 8; j++) acc[i][j] = fmaf(av[i], bw[j], acc[i][j]);
        }
        if (t + 1 < ntiles) {
#pragma unroll
            for (int it = 0; it < 2; it++) {
                int sA = tid + it * 256;
                int r = sA >> 2, kc = (sA & 3) * 4;
                As[nxt][kc + 0][r] = pa[it].x; As[nxt][kc + 1][r] = pa[it].y;
                As[nxt][kc + 2][r] = pa[it].z; As[nxt][kc + 3][r] = pa[it].w;
                int sB = tid + it * 256;
                *(float4*)&Bs[nxt][sB >> 5][(sB & 31) * 4] = pb[it];
            }
        }
        __syncthreads();
    }
#pragma unroll
    for (int i = 0; i < 4; i++) {
        int r0 = rowBase + ty * 4 + i;
        int r1 = r0 + 64;
        *(float4*)(C + (size_t)r0 * 512 + colBase + tx * 4) =
            make_float4(acc[i][0], acc[i][1], acc[i][2], acc[i][3]);
        *(float4*)(C + (size_t)r0 * 512 + colBase + tx * 4 + 64) =
            make_float4(acc[i][4], acc[i][5], acc[i][6], acc[i][7]);
        *(float4*)(C + (size_t)r1 * 512 + colBase + tx * 4) =
            make_float4(acc[i + 4][0], acc[i + 4][1], acc[i + 4][2], acc[i + 4][3]);
        *(float4*)(C + (size_t)r1 * 512 + colBase + tx * 4 + 64) =
            make_float4(acc[i + 4][4], acc[i + 4][5], acc[i + 4][6], acc[i + 4][7]);
    }
}

// ---------------- fused GCN gather + self + bias + relu + scorer dot ----------------
// one block (128 threads) per dst row; each thread owns 4 features (float4)
__global__ __launch_bounds__(128) void k_gather(const float* __restrict__ h0,
                                                float* __restrict__ out,
                                                const float* __restrict__ bias,
                                                const float* __restrict__ Wp, int n) {
    __shared__ int   nb[128];
    __shared__ float cf[128];
    __shared__ float red[4];
    const int row = blockIdx.x;
    const int b = row / n;
    const int bn = b * n;
    const int t = threadIdx.x;
    const int start = g_rowstart[row];
    const int cnt = g_cnt[row];
    const float deg = (float)(cnt + 1);
    const float dinv_d = rsqrtf(deg);

    const float4 hself = *(const float4*)(h0 + (size_t)row * NHID + t * 4);
    float4 agg = make_float4(0.f, 0.f, 0.f, 0.f);

    for (int base = 0; base < cnt; base += 128) {
        int m = min(128, cnt - base);
        if (t < m) {
            int s = g_csr[b * NEDGE + start + base + t];
            nb[t] = s;
            cf[t] = rsqrtf((float)(g_cnt[bn + s] + 1));
        }
        __syncthreads();
#pragma unroll 4
        for (int e = 0; e < m; e++) {
            const float c = cf[e];
            const float4 v = *(const float4*)(h0 + ((size_t)bn + nb[e]) * NHID + t * 4);
            agg.x = fmaf(v.x, c, agg.x);
            agg.y = fmaf(v.y, c, agg.y);
            agg.z = fmaf(v.z, c, agg.z);
            agg.w = fmaf(v.w, c, agg.w);
        }
        __syncthreads();
    }
    const float4 bb = *(const float4*)(bias + t * 4);
    float4 r;
    r.x = fmaxf(hself.x / deg + dinv_d * agg.x + bb.x, 0.0f);
    r.y = fmaxf(hself.y / deg + dinv_d * agg.y + bb.y, 0.0f);
    r.z = fmaxf(hself.z / deg + dinv_d * agg.z + bb.z, 0.0f);
    r.w = fmaxf(hself.w / deg + dinv_d * agg.w + bb.w, 0.0f);
    *(float4*)(out + (size_t)row * NHID + t * 4) = r;

    // scorer dot: s0 = relu(h) . Wp
    const float4 w = *(const float4*)(Wp + t * 4);
    float p = r.x * w.x + r.y * w.y + r.z * w.z + r.w * w.w;
#pragma unroll
    for (int o = 16; o > 0; o >>= 1) p += __shfl_down_sync(0xffffffffu, p, o);
    if ((t & 31) == 0) red[t >> 5] = p;
    __syncthreads();
    if (t == 0) g_s0[row] = red[0] + red[1] + red[2] + red[3];
}

// ---------------- score gather: warp per row ----------------
__global__ void k_score(const float* __restrict__ bp, int n) {
    int row = blockIdx.x * 8 + (threadIdx.x >> 5);
    if (row >= BATCH * n) return;
    int lane = threadIdx.x & 31;
    int b = row / n, bn = b * n;
    int start = g_rowstart[row];
    int cnt = g_cnt[row];
    float sum = 0.0f;
    for (int e = lane; e < cnt; e += 32) {
        int s = g_csr[b * NEDGE + start + e];
        sum += g_s0[bn + s] * rsqrtf((float)(g_cnt[bn + s] + 1));
    }
#pragma unroll
    for (int o = 16; o > 0; o >>= 1) sum += __shfl_down_sync(0xffffffffu, sum, o);
    if (lane == 0) {
        float deg = (float)(cnt + 1);
        g_score[row] = g_s0[row] / deg + rsqrtf(deg) * sum + bp[0];
    }
}

// ---------------- top-k: per-batch bitonic sort ----------------
__global__ void k_topk(int n, int k) {
    extern __shared__ char sm[];
    float* sv = (float*)sm;
    int* si = (int*)(sv + n);
    int b = blockIdx.x, tid = threadIdx.x;
    for (int i = tid; i < n; i += blockDim.x) { sv[i] = g_score[b * n + i]; si[i] = i; }
    __syncthreads();
    for (int ksz = 2; ksz <= n; ksz <<= 1) {
        for (int j = ksz >> 1; j > 0; j >>= 1) {
            for (int i = tid; i < n; i += blockDim.x) {
                int ixj = i ^ j;
                if (ixj > i) {
                    float v1 = sv[i], v2 = sv[ixj];
                    int i1 = si[i], i2 = si[ixj];
                    bool before = (v1 > v2) || (v1 == v2 && i1 < i2);
                    bool desc = ((i & ksz) == 0);
                    if (desc ? !before : before) {
                        sv[i] = v2; sv[ixj] = v1; si[i] = i2; si[ixj] = i1;
                    }
                }
            }
            __syncthreads();
        }
    }
    for (int i = tid; i < n; i += blockDim.x) g_newidx[b * n + i] = -1;
    __syncthreads();
    for (int t = tid; t < k; t += blockDim.x) {
        int p = si[t];
        g_perm[b * n + t] = p;
        g_newidx[b * n + p] = t;
    }
}

// ---------------- pool apply ----------------
__global__ void k_pool(const float* __restrict__ h, float* __restrict__ out, int n, int k) {
    size_t i = (size_t)blockIdx.x * blockDim.x + threadIdx.x;
    size_t total = (size_t)BATCH * k * NHID;
    if (i >= total) return;
    int f = (int)(i & 511);
    int r = (int)((i >> 9) % k);
    int b = (int)(i / ((size_t)k * NHID));
    int p = g_perm[b * n + r];
    float t = tanhf(g_score[b * n + p]);
    out[i] = h[((size_t)b * n + p) * NHID + f] * t;
}

// ---------------- readout ----------------
__global__ void k_readout(const float* __restrict__ xk, int k) {
    int b = blockIdx.x, f = threadIdx.x;   // 512 threads
    float mx = -INFINITY, sm = 0.0f;
    for (int r = 0; r < k; r++) {
        float v = xk[((size_t)b * k + r) * NHID + f];
        mx = fmaxf(mx, v);
        sm += v;
    }
    g_z[b * 1024 + f] += mx;
    g_z[b * 1024 + 512 + f] += sm / (float)k;
}

// ---------------- edge relabel ----------------
__global__ void k_edge_update(int n) {
    int i = blockIdx.x * blockDim.x + threadIdx.x;
    if (i >= BATCH * NEDGE) return;
    int b = i / NEDGE;
    if (g_em[i] != 0.0f) {
        int ns = g_newidx[b * n + g_src[i]];
        int nd = g_newidx[b * n + g_dst[i]];
        if (ns >= 0 && nd >= 0) { g_src[i] = ns; g_dst[i] = nd; }
        else { g_em[i] = 0.0f; g_src[i] = 0; g_dst[i] = 0; }
    } else { g_src[i] = 0; g_dst[i] = 0; }
}

// ---------------- head ----------------
__global__ void k_head(const float* __restrict__ l1W, const float* __restrict__ l1b,
                       const float* __restrict__ l2W, const float* __restrict__ l2b,
                       const float* __restrict__ piW, const float* __restrict__ pib,
                       const float* __restrict__ vW, const float* __restrict__ vb,
                       float* __restrict__ out) {
    __shared__ float zz[1024];
    __shared__ float z1[512];
    __shared__ float z2[256];
    __shared__ float lg[128];
    __shared__ float stats[2];
    int b = blockIdx.x, tid = threadIdx.x;   // 256 threads
    for (int i = tid; i < 1024; i += 256) zz[i] = g_z[b * 1024 + i];
    __syncthreads();
    for (int j = tid; j < 512; j += 256) {
        float a = l1b[j];
        for (int i = 0; i < 1024; i++) a = fmaf(zz[i], l1W[i * 512 + j], a);
        z1[j] = fmaxf(a, 0.0f);
    }
    __syncthreads();
    {
        int j = tid;
        float a = l2b[j];
        for (int i = 0; i < 512; i++) a = fmaf(z1[i], l2W[i * 256 + j], a);
        z2[j] = fmaxf(a, 0.0f);
    }
    __syncthreads();
    if (tid < 128) {
        float a = pib[tid];
        for (int i = 0; i < 256; i++) a = fmaf(z2[i], piW[i * 128 + tid], a);
        lg[tid] = a;
    } else if (tid == 128) {
        float a = vb[0];
        for (int i = 0; i < 256; i++) a = fmaf(z2[i], vW[i], a);
        out[BATCH * RULES + b] = fmaxf(a, 0.0f);
    }
    __syncthreads();
    if (tid == 0) {
        float mx = -INFINITY;
        for (int i = 0; i < 128; i++) mx = fmaxf(mx, lg[i]);
        float s = 0.0f;
        for (int i = 0; i < 128; i++) s += expf(lg[i] - mx);
        stats[0] = mx;
        stats[1] = logf(s);
    }
    __syncthreads();
    if (tid < 128) out[b * RULES + tid] = lg[tid] - stats[0] - stats[1];
}

// ---------------- host orchestration ----------------
static void run_stage(const float* in, float* h0buf, float* gout, float* poolout,
                      int n, int k, int K,
                      const float* W, const float* bias,
                      const float* Wp, const float* bp, bool relabel) {
    const int EB = BATCH * NEDGE;
    // CSR build
    k_zero_cnt<<<(BATCH * n + 255) / 256, 256>>>(n);
    k_count<<<(EB + 255) / 256, 256>>>(n);
    k_scan<<<BATCH, 1024>>>(n);
    k_fill<<<(EB + 255) / 256, 256>>>(n);
    // GEMM (overlaps nothing but is the big one)
    k_gemm<<<dim3(512 / 128, (BATCH * n) / 128), 256>>>(in, W, h0buf, BATCH * n, K);
    // fused gather + relu + scorer dot
    k_gather<<<BATCH * n, 128>>>(h0buf, gout, bias, Wp, n);
    k_score<<<(BATCH * n) / 8, 256>>>(bp, n);
    k_topk<<<BATCH, 1024, n * 8>>>(n, k);
    k_pool<<<(int)(((size_t)BATCH * k * NHID + 255) / 256), 256>>>(gout, poolout, n, k);
    k_readout<<<BATCH, 512>>>(poolout, k);
    if (relabel) k_edge_update<<<(EB + 255) / 256, 256>>>(n);
}

extern "C" void kernel_launch(void* const* d_in, const int* in_sizes, int n_in,
                              void* d_out, int out_size) {
    const float* x    = (const float*)d_in[0];
    const int*   src  = (const int*)d_in[1];
    const int*   dst  = (const int*)d_in[2];
    const float* W1   = (const float*)d_in[3];
    const float* b1   = (const float*)d_in[4];
    const float* Wp1  = (const float*)d_in[5];
    const float* bp1  = (const float*)d_in[6];
    const float* W2   = (const float*)d_in[7];
    const float* b2   = (const float*)d_in[8];
    const float* Wp2  = (const float*)d_in[9];
    const float* bp2  = (const float*)d_in[10];
    const float* W3   = (const float*)d_in[11];
    const float* b3   = (const float*)d_in[12];
    const float* Wp3  = (const float*)d_in[13];
    const float* bp3  = (const float*)d_in[14];
    const float* l1W  = (const float*)d_in[15];
    const float* l1b  = (const float*)d_in[16];
    const float* l2W  = (const float*)d_in[17];
    const float* l2b  = (const float*)d_in[18];
    const float* piW  = (const float*)d_in[19];
    const float* pib  = (const float*)d_in[20];
    const float* vW   = (const float*)d_in[21];
    const float* vb   = (const float*)d_in[22];
    float* out = (float*)d_out;

    float *pA = nullptr, *pB = nullptr;
    cudaGetSymbolAddress((void**)&pA, g_bufA);
    cudaGetSymbolAddress((void**)&pB, g_bufB);

    k_init_edges<<<(BATCH * NEDGE + 255) / 256, 256>>>(src, dst);
    k_zero_z<<<(BATCH * 2 * NHID + 255) / 256, 256>>>();

    // stage 1: x(2048,256) -> h0=A, gcn=B, pool -> A (1024 nodes)
    run_stage(x,  pA, pB, pA, 2048, 1024, FIN,  W1, b1, Wp1, bp1, true);
    // stage 2: A(1024,512) -> h0=B, gcn=A, pool -> B (512 nodes)
    run_stage(pA, pB, pA, pB, 1024, 512,  NHID, W2, b2, Wp2, bp2, true);
    // stage 3: B(512,512) -> h0=A, gcn=B, pool -> A (256 nodes)
    run_stage(pB, pA, pB, pA, 512,  256,  NHID, W3, b3, Wp3, bp3, false);

    k_head<<<BATCH, 256>>>(l1W, l1b, l2W, l2b, piW, pib, vW, vb, out);
}

// round 6
// speedup vs baseline: 2.9328x; 1.3383x over previous
#include <cuda_runtime.h>
#include <cuda_bf16.h>
#include <math.h>
#include <stdint.h>

#define BATCH 64
#define NMAX  2048
#define NEDGE 32768
#define FIN   256
#define NHID  512
#define RULES 128

// ---------------- scratch (device globals; no allocations) ----------------
static __device__ float g_bufA[(size_t)BATCH * NMAX * NHID];   // 256 MB
static __device__ float g_bufB[(size_t)BATCH * NMAX * NHID];   // 256 MB
// split activation buffers: must hold max(B*N*FIN, B*K1*NHID) = 33.5M elements
static __device__ __align__(16) __nv_bfloat16 g_ahi[(size_t)BATCH * NMAX * NHID / 2];
static __device__ __align__(16) __nv_bfloat16 g_alo[(size_t)BATCH * NMAX * NHID / 2];
static __device__ __align__(16) __nv_bfloat16 g_whi[NHID * NHID];
static __device__ __align__(16) __nv_bfloat16 g_wlo[NHID * NHID];
static __device__ int   g_cnt[BATCH * NMAX];
static __device__ int   g_rowstart[BATCH * NMAX];
static __device__ int   g_cursor[BATCH * NMAX];
static __device__ int   g_csr[BATCH * NEDGE];
static __device__ float g_s0[BATCH * NMAX];
static __device__ float g_score[BATCH * NMAX];
static __device__ int   g_perm[BATCH * NMAX];
static __device__ int   g_newidx[BATCH * NMAX];
static __device__ int   g_src[BATCH * NEDGE];
static __device__ int   g_dst[BATCH * NEDGE];
static __device__ float g_em[BATCH * NEDGE];
static __device__ float g_z[BATCH * 2 * NHID];

// ---------------- helpers ----------------
__device__ __forceinline__ uint32_t smem_u32(const void* p) {
    uint32_t a;
    asm("{ .reg .u64 t; cvta.to.shared.u64 t, %1; cvt.u32.u64 %0, t; }" : "=r"(a) : "l"(p));
    return a;
}
__device__ __forceinline__ void cp16(uint32_t saddr, const void* gptr) {
    asm volatile("cp.async.cg.shared.global [%0], [%1], 16;"
                 :: "r"(saddr), "l"(__cvta_generic_to_global(gptr)) : "memory");
}
__device__ __forceinline__ void ldsm4(uint32_t& r0, uint32_t& r1, uint32_t& r2, uint32_t& r3,
                                      uint32_t addr) {
    asm volatile("ldmatrix.sync.aligned.m8n8.x4.shared.b16 {%0,%1,%2,%3}, [%4];"
                 : "=r"(r0), "=r"(r1), "=r"(r2), "=r"(r3) : "r"(addr));
}
__device__ __forceinline__ void mma_bf16(float* c, uint32_t a0, uint32_t a1, uint32_t a2,
                                         uint32_t a3, uint32_t b0, uint32_t b1) {
    asm volatile(
        "mma.sync.aligned.m16n8k16.row.col.f32.bf16.bf16.f32 "
        "{%0,%1,%2,%3}, {%4,%5,%6,%7}, {%8,%9}, {%0,%1,%2,%3};"
        : "+f"(c[0]), "+f"(c[1]), "+f"(c[2]), "+f"(c[3])
        : "r"(a0), "r"(a1), "r"(a2), "r"(a3), "r"(b0), "r"(b1));
}

// ---------------- init ----------------
__global__ void k_init_edges(const int* __restrict__ src, const int* __restrict__ dst) {
    int i = blockIdx.x * blockDim.x + threadIdx.x;
    if (i < BATCH * NEDGE) { g_src[i] = src[i]; g_dst[i] = dst[i]; g_em[i] = 1.0f; }
}
__global__ void k_zero_z() {
    int i = blockIdx.x * blockDim.x + threadIdx.x;
    if (i < BATCH * 2 * NHID) g_z[i] = 0.0f;
}

// ---------------- CSR build ----------------
__global__ void k_zero_cnt(int n) {
    int i = blockIdx.x * blockDim.x + threadIdx.x;
    if (i < BATCH * n) g_cnt[i] = 0;
}
__global__ void k_count(int n) {
    int i = blockIdx.x * blockDim.x + threadIdx.x;
    if (i >= BATCH * NEDGE) return;
    if (g_em[i] != 0.0f) {
        int b = i / NEDGE;
        atomicAdd(&g_cnt[b * n + g_dst[i]], 1);
    }
}
__global__ void k_scan(int n) {
    __shared__ int buf[2][NMAX];
    int b = blockIdx.x, tid = threadIdx.x;
    for (int i = tid; i < n; i += 1024) buf[0][i] = g_cnt[b * n + i];
    __syncthreads();
    int s = 0;
    for (int d = 1; d < n; d <<= 1) {
        for (int i = tid; i < n; i += 1024) {
            int v = buf[s][i];
            if (i >= d) v += buf[s][i - d];
            buf[s ^ 1][i] = v;
        }
        __syncthreads();
        s ^= 1;
    }
    for (int i = tid; i < n; i += 1024) {
        int excl = (i == 0) ? 0 : buf[s][i - 1];
        g_rowstart[b * n + i] = excl;
        g_cursor[b * n + i] = excl;
    }
}
__global__ void k_fill(int n) {
    int i = blockIdx.x * blockDim.x + threadIdx.x;
    if (i >= BATCH * NEDGE) return;
    if (g_em[i] == 0.0f) return;
    int b = i / NEDGE;
    int pos = atomicAdd(&g_cursor[b * n + g_dst[i]], 1);
    g_csr[b * NEDGE + pos] = g_src[i];
}

// ---------------- fp32 -> bf16 split (hi + lo) ----------------
__global__ void k_split_a(const float* __restrict__ in, __nv_bfloat16* __restrict__ hi,
                          __nv_bfloat16* __restrict__ lo, size_t total) {
    size_t i = (size_t)blockIdx.x * blockDim.x + threadIdx.x;
    if (i >= total) return;
    float v = in[i];
    __nv_bfloat16 h = __float2bfloat16(v);
    hi[i] = h;
    lo[i] = __float2bfloat16(v - __bfloat162float(h));
}
// W[K,512] -> Wt split [512,K]  (i.e. B in [N,K] = col-major for mma row.col)
__global__ void k_split_w(const float* __restrict__ W, __nv_bfloat16* __restrict__ hi,
                          __nv_bfloat16* __restrict__ lo, int K) {
    int i = blockIdx.x * blockDim.x + threadIdx.x;
    if (i >= 512 * K) return;
    int nn = i / K, k = i - nn * K;
    float v = W[(size_t)k * 512 + nn];
    __nv_bfloat16 h = __float2bfloat16(v);
    hi[i] = h;
    lo[i] = __float2bfloat16(v - __bfloat162float(h));
}

// ---------------- split-bf16 tensor GEMM via mma.sync ----------------
// C[M,512] = A[M,K] @ W[K,512];  A = Ahi+Alo [M,K] row-major, B = W^T hi/lo [512,K].
// C = Ahi@Bhi + Ahi@Blo + Alo@Bhi  (f32 accum).
// CTA: 128x128 tile, BK=32, 8 warps (warp_m 0..3 -> 32 rows; warp_n 0..1 -> 64 cols).
#define LDS_E   40                       // row stride in elements (80 B, conflict-free phases)
#define TILE_B  (128 * LDS_E * 2)        // 10240 B per tile
#define STAGE_B (4 * TILE_B)             // Ahi,Alo,Bhi,Blo
#define GEMM_SMEM (2 * STAGE_B)          // 81920 B
__global__ __launch_bounds__(256, 1) void k_gemm_mma(
    const __nv_bfloat16* __restrict__ Ahi, const __nv_bfloat16* __restrict__ Alo,
    const __nv_bfloat16* __restrict__ Bhi, const __nv_bfloat16* __restrict__ Blo,
    float* __restrict__ C, int M, int K)
{
    extern __shared__ __align__(128) char smem[];
    const uint32_t sb = smem_u32(smem);
    const int tid = threadIdx.x;
    const int wid = tid >> 5;
    const int lane = tid & 31;
    const int warp_m = wid & 3;
    const int warp_n = wid >> 2;
    const int rowBase = blockIdx.y * 128;
    const int colBase = blockIdx.x * 128;

    // ldmatrix lane -> element mapping (m16n8k16 row.col fragment layouts)
    const int g = lane >> 3;
    const int a_m = lane & 15;
    const int a_k = (lane >> 4) << 3;
    const int b_n = lane - ((g == 0) ? 0 : (g == 3) ? 16 : 8);
    const int b_k = (g & 1) << 3;

    uint32_t aoff[2], boff[4];
#pragma unroll
    for (int mt = 0; mt < 2; mt++)
        aoff[mt] = ((warp_m * 32 + mt * 16 + a_m) * LDS_E + a_k) * 2;
#pragma unroll
    for (int ng = 0; ng < 4; ng++)
        boff[ng] = ((warp_n * 64 + ng * 16 + b_n) * LDS_E + b_k) * 2;

    float acc[2][8][4];
#pragma unroll
    for (int mt = 0; mt < 2; mt++)
#pragma unroll
        for (int nf = 0; nf < 8; nf++)
#pragma unroll
            for (int e = 0; e < 4; e++) acc[mt][nf][e] = 0.0f;

    const int nch = K >> 5;

    auto load_stage = [&](int t) {
        const uint32_t base = sb + (t & 1) * STAGE_B;
        const int kc0 = t << 5;
#pragma unroll
        for (int part = 0; part < 2; part++) {
            int idx = tid + part * 256;           // 0..511
            int r = idx >> 2, blk = idx & 3;
            uint32_t so = r * (LDS_E * 2) + blk * 16;
            size_t ga = (size_t)(rowBase + r) * K + kc0 + blk * 8;
            cp16(base + so,              Ahi + ga);
            cp16(base + TILE_B + so,     Alo + ga);
            size_t gb = (size_t)(colBase + r) * K + kc0 + blk * 8;
            cp16(base + 2 * TILE_B + so, Bhi + gb);
            cp16(base + 3 * TILE_B + so, Blo + gb);
        }
        asm volatile("cp.async.commit_group;" ::: "memory");
    };

    load_stage(0);
    for (int t = 0; t < nch; t++) {
        if (t + 1 < nch) {
            load_stage(t + 1);
            asm volatile("cp.async.wait_group 1;" ::: "memory");
        } else {
            asm volatile("cp.async.wait_group 0;" ::: "memory");
        }
        __syncthreads();
        const uint32_t base = sb + (t & 1) * STAGE_B;
#pragma unroll
        for (int kk = 0; kk < 2; kk++) {
            const uint32_t ko = kk * 32;   // 16 elems * 2 bytes
            uint32_t ah[2][4], al[2][4];
#pragma unroll
            for (int mt = 0; mt < 2; mt++) {
                ldsm4(ah[mt][0], ah[mt][1], ah[mt][2], ah[mt][3], base + aoff[mt] + ko);
                ldsm4(al[mt][0], al[mt][1], al[mt][2], al[mt][3], base + TILE_B + aoff[mt] + ko);
            }
            uint32_t bh[8][2], bl[8][2];
#pragma unroll
            for (int ng = 0; ng < 4; ng++) {
                uint32_t r0, r1, r2, r3;
                ldsm4(r0, r1, r2, r3, base + 2 * TILE_B + boff[ng] + ko);
                bh[ng * 2][0] = r0; bh[ng * 2][1] = r1;
                bh[ng * 2 + 1][0] = r2; bh[ng * 2 + 1][1] = r3;
                ldsm4(r0, r1, r2, r3, base + 3 * TILE_B + boff[ng] + ko);
                bl[ng * 2][0] = r0; bl[ng * 2][1] = r1;
                bl[ng * 2 + 1][0] = r2; bl[ng * 2 + 1][1] = r3;
            }
#pragma unroll
            for (int mt = 0; mt < 2; mt++)
#pragma unroll
                for (int nf = 0; nf < 8; nf++) {
                    mma_bf16(acc[mt][nf], ah[mt][0], ah[mt][1], ah[mt][2], ah[mt][3],
                             bh[nf][0], bh[nf][1]);
                    mma_bf16(acc[mt][nf], ah[mt][0], ah[mt][1], ah[mt][2], ah[mt][3],
                             bl[nf][0], bl[nf][1]);
                    mma_bf16(acc[mt][nf], al[mt][0], al[mt][1], al[mt][2], al[mt][3],
                             bh[nf][0], bh[nf][1]);
                }
        }
        __syncthreads();
    }

    // epilogue
#pragma unroll
    for (int mt = 0; mt < 2; mt++) {
        int r0 = rowBase + warp_m * 32 + mt * 16 + (lane >> 2);
        int r1 = r0 + 8;
#pragma unroll
        for (int nf = 0; nf < 8; nf++) {
            int col = colBase + warp_n * 64 + nf * 8 + (lane & 3) * 2;
            *(float2*)(C + (size_t)r0 * 512 + col) = make_float2(acc[mt][nf][0], acc[mt][nf][1]);
            *(float2*)(C + (size_t)r1 * 512 + col) = make_float2(acc[mt][nf][2], acc[mt][nf][3]);
        }
    }
}

// ---------------- fused GCN gather + self + bias + relu + scorer dot ----------------
__global__ __launch_bounds__(128) void k_gather(const float* __restrict__ h0,
                                                float* __restrict__ out,
                                                const float* __restrict__ bias,
                                                const float* __restrict__ Wp, int n) {
    __shared__ int   nb[128];
    __shared__ float cf[128];
    __shared__ float red[4];
    const int row = blockIdx.x;
    const int b = row / n;
    const int bn = b * n;
    const int t = threadIdx.x;
    const int start = g_rowstart[row];
    const int cnt = g_cnt[row];
    const float deg = (float)(cnt + 1);
    const float dinv_d = rsqrtf(deg);

    const float4 hself = *(const float4*)(h0 + (size_t)row * NHID + t * 4);
    float4 agg = make_float4(0.f, 0.f, 0.f, 0.f);

    for (int base = 0; base < cnt; base += 128) {
        int m = min(128, cnt - base);
        if (t < m) {
            int s = g_csr[b * NEDGE + start + base + t];
            nb[t] = s;
            cf[t] = rsqrtf((float)(g_cnt[bn + s] + 1));
        }
        __syncthreads();
#pragma unroll 4
        for (int e = 0; e < m; e++) {
            const float c = cf[e];
            const float4 v = *(const float4*)(h0 + ((size_t)bn + nb[e]) * NHID + t * 4);
            agg.x = fmaf(v.x, c, agg.x);
            agg.y = fmaf(v.y, c, agg.y);
            agg.z = fmaf(v.z, c, agg.z);
            agg.w = fmaf(v.w, c, agg.w);
        }
        __syncthreads();
    }
    const float4 bb = *(const float4*)(bias + t * 4);
    float4 r;
    r.x = fmaxf(hself.x / deg + dinv_d * agg.x + bb.x, 0.0f);
    r.y = fmaxf(hself.y / deg + dinv_d * agg.y + bb.y, 0.0f);
    r.z = fmaxf(hself.z / deg + dinv_d * agg.z + bb.z, 0.0f);
    r.w = fmaxf(hself.w / deg + dinv_d * agg.w + bb.w, 0.0f);
    *(float4*)(out + (size_t)row * NHID + t * 4) = r;

    const float4 w = *(const float4*)(Wp + t * 4);
    float p = r.x * w.x + r.y * w.y + r.z * w.z + r.w * w.w;
#pragma unroll
    for (int o = 16; o > 0; o >>= 1) p += __shfl_down_sync(0xffffffffu, p, o);
    if ((t & 31) == 0) red[t >> 5] = p;
    __syncthreads();
    if (t == 0) g_s0[row] = red[0] + red[1] + red[2] + red[3];
}

// ---------------- score gather ----------------
__global__ void k_score(const float* __restrict__ bp, int n) {
    int row = blockIdx.x * 8 + (threadIdx.x >> 5);
    if (row >= BATCH * n) return;
    int lane = threadIdx.x & 31;
    int b = row / n, bn = b * n;
    int start = g_rowstart[row];
    int cnt = g_cnt[row];
    float sum = 0.0f;
    for (int e = lane; e < cnt; e += 32) {
        int s = g_csr[b * NEDGE + start + e];
        sum += g_s0[bn + s] * rsqrtf((float)(g_cnt[bn + s] + 1));
    }
#pragma unroll
    for (int o = 16; o > 0; o >>= 1) sum += __shfl_down_sync(0xffffffffu, sum, o);
    if (lane == 0) {
        float deg = (float)(cnt + 1);
        g_score[row] = g_s0[row] / deg + rsqrtf(deg) * sum + bp[0];
    }
}

// ---------------- top-k: per-batch bitonic sort ----------------
__global__ void k_topk(int n, int k) {
    extern __shared__ char sm[];
    float* sv = (float*)sm;
    int* si = (int*)(sv + n);
    int b = blockIdx.x, tid = threadIdx.x;
    for (int i = tid; i < n; i += blockDim.x) { sv[i] = g_score[b * n + i]; si[i] = i; }
    __syncthreads();
    for (int ksz = 2; ksz <= n; ksz <<= 1) {
        for (int j = ksz >> 1; j > 0; j >>= 1) {
            for (int i = tid; i < n; i += blockDim.x) {
                int ixj = i ^ j;
                if (ixj > i) {
                    float v1 = sv[i], v2 = sv[ixj];
                    int i1 = si[i], i2 = si[ixj];
                    bool before = (v1 > v2) || (v1 == v2 && i1 < i2);
                    bool desc = ((i & ksz) == 0);
                    if (desc ? !before : before) {
                        sv[i] = v2; sv[ixj] = v1; si[i] = i2; si[ixj] = i1;
                    }
                }
            }
            __syncthreads();
        }
    }
    for (int i = tid; i < n; i += blockDim.x) g_newidx[b * n + i] = -1;
    __syncthreads();
    for (int t = tid; t < k; t += blockDim.x) {
        int p = si[t];
        g_perm[b * n + t] = p;
        g_newidx[b * n + p] = t;
    }
}

// ---------------- pool apply (+ fused bf16 split for next GEMM) ----------------
__global__ void k_pool(const float* __restrict__ h, float* __restrict__ out,
                       __nv_bfloat16* __restrict__ hi, __nv_bfloat16* __restrict__ lo,
                       int n, int k) {
    size_t i = (size_t)blockIdx.x * blockDim.x + threadIdx.x;
    size_t total = (size_t)BATCH * k * NHID;
    if (i >= total) return;
    int f = (int)(i & 511);
    int r = (int)((i >> 9) % k);
    int b = (int)(i / ((size_t)k * NHID));
    int p = g_perm[b * n + r];
    float t = tanhf(g_score[b * n + p]);
    float v = h[((size_t)b * n + p) * NHID + f] * t;
    out[i] = v;
    if (hi) {
        __nv_bfloat16 vh = __float2bfloat16(v);
        hi[i] = vh;
        lo[i] = __float2bfloat16(v - __bfloat162float(vh));
    }
}

// ---------------- readout ----------------
__global__ void k_readout(const float* __restrict__ xk, int k) {
    int b = blockIdx.x, f = threadIdx.x;
    float mx = -INFINITY, sm = 0.0f;
    for (int r = 0; r < k; r++) {
        float v = xk[((size_t)b * k + r) * NHID + f];
        mx = fmaxf(mx, v);
        sm += v;
    }
    g_z[b * 1024 + f] += mx;
    g_z[b * 1024 + 512 + f] += sm / (float)k;
}

// ---------------- edge relabel ----------------
__global__ void k_edge_update(int n) {
    int i = blockIdx.x * blockDim.x + threadIdx.x;
    if (i >= BATCH * NEDGE) return;
    int b = i / NEDGE;
    if (g_em[i] != 0.0f) {
        int ns = g_newidx[b * n + g_src[i]];
        int nd = g_newidx[b * n + g_dst[i]];
        if (ns >= 0 && nd >= 0) { g_src[i] = ns; g_dst[i] = nd; }
        else { g_em[i] = 0.0f; g_src[i] = 0; g_dst[i] = 0; }
    } else { g_src[i] = 0; g_dst[i] = 0; }
}

// ---------------- head ----------------
__global__ void k_head(const float* __restrict__ l1W, const float* __restrict__ l1b,
                       const float* __restrict__ l2W, const float* __restrict__ l2b,
                       const float* __restrict__ piW, const float* __restrict__ pib,
                       const float* __restrict__ vW, const float* __restrict__ vb,
                       float* __restrict__ out) {
    __shared__ float zz[1024];
    __shared__ float z1[512];
    __shared__ float z2[256];
    __shared__ float lg[128];
    __shared__ float stats[2];
    int b = blockIdx.x, tid = threadIdx.x;
    for (int i = tid; i < 1024; i += 256) zz[i] = g_z[b * 1024 + i];
    __syncthreads();
    for (int j = tid; j < 512; j += 256) {
        float a = l1b[j];
        for (int i = 0; i < 1024; i++) a = fmaf(zz[i], l1W[i * 512 + j], a);
        z1[j] = fmaxf(a, 0.0f);
    }
    __syncthreads();
    {
        int j = tid;
        float a = l2b[j];
        for (int i = 0; i < 512; i++) a = fmaf(z1[i], l2W[i * 256 + j], a);
        z2[j] = fmaxf(a, 0.0f);
    }
    __syncthreads();
    if (tid < 128) {
        float a = pib[tid];
        for (int i = 0; i < 256; i++) a = fmaf(z2[i], piW[i * 128 + tid], a);
        lg[tid] = a;
    } else if (tid == 128) {
        float a = vb[0];
        for (int i = 0; i < 256; i++) a = fmaf(z2[i], vW[i], a);
        out[BATCH * RULES + b] = fmaxf(a, 0.0f);
    }
    __syncthreads();
    if (tid == 0) {
        float mx = -INFINITY;
        for (int i = 0; i < 128; i++) mx = fmaxf(mx, lg[i]);
        float s = 0.0f;
        for (int i = 0; i < 128; i++) s += expf(lg[i] - mx);
        stats[0] = mx;
        stats[1] = logf(s);
    }
    __syncthreads();
    if (tid < 128) out[b * RULES + tid] = lg[tid] - stats[0] - stats[1];
}

// ---------------- host orchestration ----------------
static void run_stage(float* h0buf, float* gout, float* poolout,
                      __nv_bfloat16* ahi, __nv_bfloat16* alo,
                      __nv_bfloat16* whi, __nv_bfloat16* wlo,
                      int n, int k, int K,
                      const float* W, const float* bias,
                      const float* Wp, const float* bp, bool relabel,
                      bool split_next) {
    const int EB = BATCH * NEDGE;
    // CSR build
    k_zero_cnt<<<(BATCH * n + 255) / 256, 256>>>(n);
    k_count<<<(EB + 255) / 256, 256>>>(n);
    k_scan<<<BATCH, 1024>>>(n);
    k_fill<<<(EB + 255) / 256, 256>>>(n);
    // weight split (transposed -> [512,K])
    k_split_w<<<(512 * K + 255) / 256, 256>>>(W, whi, wlo, K);
    // tensor-core GEMM (mma.sync)
    k_gemm_mma<<<dim3(4, (BATCH * n) / 128), 256, GEMM_SMEM>>>(ahi, alo, whi, wlo, h0buf,
                                                               BATCH * n, K);
    // fused gather + relu + scorer dot
    k_gather<<<BATCH * n, 128>>>(h0buf, gout, bias, Wp, n);
    k_score<<<(BATCH * n) / 8, 256>>>(bp, n);
    k_topk<<<BATCH, 1024, n * 8>>>(n, k);
    k_pool<<<(int)(((size_t)BATCH * k * NHID + 255) / 256), 256>>>(
        gout, poolout, split_next ? ahi : (__nv_bfloat16*)nullptr,
        split_next ? alo : (__nv_bfloat16*)nullptr, n, k);
    k_readout<<<BATCH, 512>>>(poolout, k);
    if (relabel) k_edge_update<<<(EB + 255) / 256, 256>>>(n);
}

extern "C" void kernel_launch(void* const* d_in, const int* in_sizes, int n_in,
                              void* d_out, int out_size) {
    const float* x    = (const float*)d_in[0];
    const int*   src  = (const int*)d_in[1];
    const int*   dst  = (const int*)d_in[2];
    const float* W1   = (const float*)d_in[3];
    const float* b1   = (const float*)d_in[4];
    const float* Wp1  = (const float*)d_in[5];
    const float* bp1  = (const float*)d_in[6];
    const float* W2   = (const float*)d_in[7];
    const float* b2   = (const float*)d_in[8];
    const float* Wp2  = (const float*)d_in[9];
    const float* bp2  = (const float*)d_in[10];
    const float* W3   = (const float*)d_in[11];
    const float* b3   = (const float*)d_in[12];
    const float* Wp3  = (const float*)d_in[13];
    const float* bp3  = (const float*)d_in[14];
    const float* l1W  = (const float*)d_in[15];
    const float* l1b  = (const float*)d_in[16];
    const float* l2W  = (const float*)d_in[17];
    const float* l2b  = (const float*)d_in[18];
    const float* piW  = (const float*)d_in[19];
    const float* pib  = (const float*)d_in[20];
    const float* vW   = (const float*)d_in[21];
    const float* vb   = (const float*)d_in[22];
    float* out = (float*)d_out;

    float *pA = nullptr, *pB = nullptr;
    __nv_bfloat16 *ahi = nullptr, *alo = nullptr, *whi = nullptr, *wlo = nullptr;
    cudaGetSymbolAddress((void**)&pA, g_bufA);
    cudaGetSymbolAddress((void**)&pB, g_bufB);
    cudaGetSymbolAddress((void**)&ahi, g_ahi);
    cudaGetSymbolAddress((void**)&alo, g_alo);
    cudaGetSymbolAddress((void**)&whi, g_whi);
    cudaGetSymbolAddress((void**)&wlo, g_wlo);

    cudaFuncSetAttribute(k_gemm_mma, cudaFuncAttributeMaxDynamicSharedMemorySize, GEMM_SMEM);

    k_init_edges<<<(BATCH * NEDGE + 255) / 256, 256>>>(src, dst);
    k_zero_z<<<(BATCH * 2 * NHID + 255) / 256, 256>>>();
    // split the stage-1 activation input (33.5M elements)
    k_split_a<<<(int)(((size_t)BATCH * NMAX * FIN + 255) / 256), 256>>>(
        x, ahi, alo, (size_t)BATCH * NMAX * FIN);

    // stage 1: 2048 nodes, K=256 -> h0=A, gcn=B, pool -> A (1024 nodes) + split into ahi/alo
    run_stage(pA, pB, pA, ahi, alo, whi, wlo, 2048, 1024, FIN,  W1, b1, Wp1, bp1, true,  true);
    // stage 2: 1024 nodes -> h0=B, gcn=A, pool -> B (512 nodes) + split
    run_stage(pB, pA, pB, ahi, alo, whi, wlo, 1024, 512,  NHID, W2, b2, Wp2, bp2, true,  true);
    // stage 3: 512 nodes -> h0=A, gcn=B, pool -> A (256 nodes), no split needed
    run_stage(pA, pB, pA, ahi, alo, whi, wlo, 512,  256,  NHID, W3, b3, Wp3, bp3, false, false);

    k_head<<<BATCH, 256>>>(l1W, l1b, l2W, l2b, piW, pib, vW, vb, out);
}

// round 7
// speedup vs baseline: 3.1252x; 1.0656x over previous
#include <cuda_runtime.h>
#include <cuda_bf16.h>
#include <math.h>
#include <stdint.h>

#define BATCH 64
#define NMAX  2048
#define NEDGE 32768
#define FIN   256
#define NHID  512
#define RULES 128

// ---------------- scratch (device globals; no allocations) ----------------
static __device__ float g_bufA[(size_t)BATCH * NMAX * NHID];   // 256 MB
static __device__ float g_bufB[(size_t)BATCH * NMAX * NHID];   // 256 MB
// split activation buffers: hold max(B*N*FIN, B*K1*NHID) = 33.5M elements
static __device__ __align__(16) __nv_bfloat16 g_ahi[(size_t)BATCH * NMAX * NHID / 2];
static __device__ __align__(16) __nv_bfloat16 g_alo[(size_t)BATCH * NMAX * NHID / 2];
static __device__ __align__(16) __nv_bfloat16 g_whi[NHID * NHID];
static __device__ __align__(16) __nv_bfloat16 g_wlo[NHID * NHID];
static __device__ int   g_cnt[BATCH * NMAX];
static __device__ int   g_rowstart[BATCH * NMAX];
static __device__ int   g_csr[BATCH * NEDGE];
static __device__ float g_s0[BATCH * NMAX];
static __device__ float g_score[BATCH * NMAX];
static __device__ int   g_perm[BATCH * NMAX];
static __device__ int   g_newidx[BATCH * NMAX];
static __device__ int   g_src[BATCH * NEDGE];
static __device__ int   g_dst[BATCH * NEDGE];
static __device__ float g_em[BATCH * NEDGE];
static __device__ float g_z[BATCH * 2 * NHID];

// ---------------- helpers ----------------
__device__ __forceinline__ uint32_t smem_u32(const void* p) {
    uint32_t a;
    asm("{ .reg .u64 t; cvta.to.shared.u64 t, %1; cvt.u32.u64 %0, t; }" : "=r"(a) : "l"(p));
    return a;
}
__device__ __forceinline__ void cp16(uint32_t saddr, const void* gptr) {
    asm volatile("cp.async.cg.shared.global [%0], [%1], 16;"
                 :: "r"(saddr), "l"(__cvta_generic_to_global(gptr)) : "memory");
}
__device__ __forceinline__ void ldsm4(uint32_t& r0, uint32_t& r1, uint32_t& r2, uint32_t& r3,
                                      uint32_t addr) {
    asm volatile("ldmatrix.sync.aligned.m8n8.x4.shared.b16 {%0,%1,%2,%3}, [%4];"
                 : "=r"(r0), "=r"(r1), "=r"(r2), "=r"(r3) : "r"(addr));
}
__device__ __forceinline__ void mma_bf16(float* c, uint32_t a0, uint32_t a1, uint32_t a2,
                                         uint32_t a3, uint32_t b0, uint32_t b1) {
    asm volatile(
        "mma.sync.aligned.m16n8k16.row.col.f32.bf16.bf16.f32 "
        "{%0,%1,%2,%3}, {%4,%5,%6,%7}, {%8,%9}, {%0,%1,%2,%3};"
        : "+f"(c[0]), "+f"(c[1]), "+f"(c[2]), "+f"(c[3])
        : "r"(a0), "r"(a1), "r"(a2), "r"(a3), "r"(b0), "r"(b1));
}

// ---------------- init (stage-1 count fused in) ----------------
__global__ void k_zero_cnt(int total) {
    int i = blockIdx.x * blockDim.x + threadIdx.x;
    if (i < total) g_cnt[i] = 0;
}
__global__ void k_init_edges_count(const int* __restrict__ src, const int* __restrict__ dst) {
    int i = blockIdx.x * blockDim.x + threadIdx.x;
    if (i >= BATCH * NEDGE) return;
    int s = src[i], d = dst[i];
    g_src[i] = s; g_dst[i] = d; g_em[i] = 1.0f;
    int b = i / NEDGE;
    atomicAdd(&g_cnt[b * NMAX + d], 1);
}
__global__ void k_zero_z() {
    int i = blockIdx.x * blockDim.x + threadIdx.x;
    if (i < BATCH * 2 * NHID) g_z[i] = 0.0f;
}

// ---------------- fused per-batch scan + CSR fill (shared-mem cursors) ----------------
__global__ __launch_bounds__(1024) void k_scan_fill(int n) {
    __shared__ int buf[2][NMAX];
    __shared__ int cur[NMAX];
    int b = blockIdx.x, tid = threadIdx.x;
    for (int i = tid; i < n; i += 1024) buf[0][i] = g_cnt[b * n + i];
    __syncthreads();
    int s = 0;
    for (int d = 1; d < n; d <<= 1) {
        for (int i = tid; i < n; i += 1024) {
            int v = buf[s][i];
            if (i >= d) v += buf[s][i - d];
            buf[s ^ 1][i] = v;
        }
        __syncthreads();
        s ^= 1;
    }
    for (int i = tid; i < n; i += 1024) {
        int excl = (i == 0) ? 0 : buf[s][i - 1];
        g_rowstart[b * n + i] = excl;
        cur[i] = excl;
    }
    __syncthreads();
    for (int e = tid; e < NEDGE; e += 1024) {
        int i = b * NEDGE + e;
        if (g_em[i] != 0.0f) {
            int pos = atomicAdd(&cur[g_dst[i]], 1);
            g_csr[b * NEDGE + pos] = g_src[i];
        }
    }
}

// ---------------- fp32 -> bf16 split (hi + lo) ----------------
__global__ void k_split_a(const float* __restrict__ in, __nv_bfloat16* __restrict__ hi,
                          __nv_bfloat16* __restrict__ lo, size_t total) {
    size_t i = (size_t)blockIdx.x * blockDim.x + threadIdx.x;
    if (i >= total) return;
    float v = in[i];
    __nv_bfloat16 h = __float2bfloat16(v);
    hi[i] = h;
    lo[i] = __float2bfloat16(v - __bfloat162float(h));
}
__global__ void k_split_w(const float* __restrict__ W, __nv_bfloat16* __restrict__ hi,
                          __nv_bfloat16* __restrict__ lo, int K) {
    int i = blockIdx.x * blockDim.x + threadIdx.x;
    if (i >= 512 * K) return;
    int nn = i / K, k = i - nn * K;
    float v = W[(size_t)k * 512 + nn];
    __nv_bfloat16 h = __float2bfloat16(v);
    hi[i] = h;
    lo[i] = __float2bfloat16(v - __bfloat162float(h));
}

// ---------------- split-bf16 tensor GEMM via mma.sync ----------------
// C[M,512] = A[M,K] @ W[K,512].  C = Ahi@Bhi + Ahi@Blo + Alo@Bhi  (f32 accum).
// CTA: 128x256 tile, BK=32, 512 threads / 16 warps (warp_m 0..3 x warp_n 0..3, 32x64 each).
#define LDS_E   40                        // row stride elems (80 B, conflict-free phases)
#define TILE_A  (128 * LDS_E * 2)         // 10240 B
#define TILE_BS (256 * LDS_E * 2)         // 20480 B
#define STAGE_B (2 * TILE_A + 2 * TILE_BS)  // 61440 B
#define GEMM_SMEM (2 * STAGE_B)             // 122880 B
__global__ __launch_bounds__(512, 1) void k_gemm_mma(
    const __nv_bfloat16* __restrict__ Ahi, const __nv_bfloat16* __restrict__ Alo,
    const __nv_bfloat16* __restrict__ Bhi, const __nv_bfloat16* __restrict__ Blo,
    float* __restrict__ C, int M, int K)
{
    extern __shared__ __align__(128) char smem[];
    const uint32_t sb = smem_u32(smem);
    const int tid = threadIdx.x;
    const int wid = tid >> 5;
    const int lane = tid & 31;
    const int warp_m = wid & 3;
    const int warp_n = wid >> 2;
    const int rowBase = blockIdx.y * 128;
    const int colBase = blockIdx.x * 256;

    // ldmatrix lane -> element mapping (m16n8k16 row.col fragment layouts)
    const int g = lane >> 3;
    const int a_m = lane & 15;
    const int a_k = (lane >> 4) << 3;
    const int b_n = lane - ((g == 0) ? 0 : (g == 3) ? 16 : 8);
    const int b_k = (g & 1) << 3;

    uint32_t aoff[2], boff[4];
#pragma unroll
    for (int mt = 0; mt < 2; mt++)
        aoff[mt] = ((warp_m * 32 + mt * 16 + a_m) * LDS_E + a_k) * 2;
#pragma unroll
    for (int ng = 0; ng < 4; ng++)
        boff[ng] = ((warp_n * 64 + ng * 16 + b_n) * LDS_E + b_k) * 2;

    float acc[2][8][4];
#pragma unroll
    for (int mt = 0; mt < 2; mt++)
#pragma unroll
        for (int nf = 0; nf < 8; nf++)
#pragma unroll
            for (int e = 0; e < 4; e++) acc[mt][nf][e] = 0.0f;

    const int nch = K >> 5;

    auto load_stage = [&](int t) {
        const uint32_t base = sb + (t & 1) * STAGE_B;
        const int kc0 = t << 5;
        {   // A tiles: 512 cp16 each for hi/lo
            int r = tid >> 2, blk = tid & 3;
            uint32_t so = r * (LDS_E * 2) + blk * 16;
            size_t ga = (size_t)(rowBase + r) * K + kc0 + blk * 8;
            cp16(base + so,          Ahi + ga);
            cp16(base + TILE_A + so, Alo + ga);
        }
#pragma unroll
        for (int part = 0; part < 2; part++) {   // B tiles: 1024 cp16 each for hi/lo
            int idx = tid + part * 512;
            int r = idx >> 2, blk = idx & 3;
            uint32_t so = r * (LDS_E * 2) + blk * 16;
            size_t gb = (size_t)(colBase + r) * K + kc0 + blk * 8;
            cp16(base + 2 * TILE_A + so,           Bhi + gb);
            cp16(base + 2 * TILE_A + TILE_BS + so, Blo + gb);
        }
        asm volatile("cp.async.commit_group;" ::: "memory");
    };

    load_stage(0);
    for (int t = 0; t < nch; t++) {
        if (t + 1 < nch) {
            load_stage(t + 1);
            asm volatile("cp.async.wait_group 1;" ::: "memory");
        } else {
            asm volatile("cp.async.wait_group 0;" ::: "memory");
        }
        __syncthreads();
        const uint32_t base = sb + (t & 1) * STAGE_B;
        const uint32_t bbase = base + 2 * TILE_A;
#pragma unroll
        for (int kk = 0; kk < 2; kk++) {
            const uint32_t ko = kk * 32;   // 16 elems * 2 bytes
            uint32_t ah[2][4], al[2][4];
#pragma unroll
            for (int mt = 0; mt < 2; mt++) {
                ldsm4(ah[mt][0], ah[mt][1], ah[mt][2], ah[mt][3], base + aoff[mt] + ko);
                ldsm4(al[mt][0], al[mt][1], al[mt][2], al[mt][3], base + TILE_A + aoff[mt] + ko);
            }
            // two nf-halves to bound register liveness
#pragma unroll
            for (int half = 0; half < 2; half++) {
                uint32_t bh[4][2], bl[4][2];
#pragma unroll
                for (int gg = 0; gg < 2; gg++) {
                    int ng = half * 2 + gg;
                    uint32_t r0, r1, r2, r3;
                    ldsm4(r0, r1, r2, r3, bbase + boff[ng] + ko);
                    bh[gg * 2][0] = r0; bh[gg * 2][1] = r1;
                    bh[gg * 2 + 1][0] = r2; bh[gg * 2 + 1][1] = r3;
                    ldsm4(r0, r1, r2, r3, bbase + TILE_BS + boff[ng] + ko);
                    bl[gg * 2][0] = r0; bl[gg * 2][1] = r1;
                    bl[gg * 2 + 1][0] = r2; bl[gg * 2 + 1][1] = r3;
                }
#pragma unroll
                for (int mt = 0; mt < 2; mt++)
#pragma unroll
                    for (int q = 0; q < 4; q++) {
                        int nf = half * 4 + q;
                        mma_bf16(acc[mt][nf], ah[mt][0], ah[mt][1], ah[mt][2], ah[mt][3],
                                 bh[q][0], bh[q][1]);
                        mma_bf16(acc[mt][nf], ah[mt][0], ah[mt][1], ah[mt][2], ah[mt][3],
                                 bl[q][0], bl[q][1]);
                        mma_bf16(acc[mt][nf], al[mt][0], al[mt][1], al[mt][2], al[mt][3],
                                 bh[q][0], bh[q][1]);
                    }
            }
        }
        __syncthreads();
    }

    // epilogue
#pragma unroll
    for (int mt = 0; mt < 2; mt++) {
        int r0 = rowBase + warp_m * 32 + mt * 16 + (lane >> 2);
        int r1 = r0 + 8;
#pragma unroll
        for (int nf = 0; nf < 8; nf++) {
            int col = colBase + warp_n * 64 + nf * 8 + (lane & 3) * 2;
            *(float2*)(C + (size_t)r0 * 512 + col) = make_float2(acc[mt][nf][0], acc[mt][nf][1]);
            *(float2*)(C + (size_t)r1 * 512 + col) = make_float2(acc[mt][nf][2], acc[mt][nf][3]);
        }
    }
}

// ---------------- fused GCN gather + self + bias + relu + scorer dot ----------------
__global__ __launch_bounds__(128) void k_gather(const float* __restrict__ h0,
                                                float* __restrict__ out,
                                                const float* __restrict__ bias,
                                                const float* __restrict__ Wp, int n) {
    __shared__ int   nb[128];
    __shared__ float cf[128];
    __shared__ float red[4];
    const int row = blockIdx.x;
    const int b = row / n;
    const int bn = b * n;
    const int t = threadIdx.x;
    const int start = g_rowstart[row];
    const int cnt = g_cnt[row];
    const float deg = (float)(cnt + 1);
    const float dinv_d = rsqrtf(deg);

    const float4 hself = *(const float4*)(h0 + (size_t)row * NHID + t * 4);
    float4 agg = make_float4(0.f, 0.f, 0.f, 0.f);

    for (int base = 0; base < cnt; base += 128) {
        int m = min(128, cnt - base);
        if (t < m) {
            int s = g_csr[b * NEDGE + start + base + t];
            nb[t] = s;
            cf[t] = rsqrtf((float)(g_cnt[bn + s] + 1));
        }
        __syncthreads();
#pragma unroll 4
        for (int e = 0; e < m; e++) {
            const float c = cf[e];
            const float4 v = *(const float4*)(h0 + ((size_t)bn + nb[e]) * NHID + t * 4);
            agg.x = fmaf(v.x, c, agg.x);
            agg.y = fmaf(v.y, c, agg.y);
            agg.z = fmaf(v.z, c, agg.z);
            agg.w = fmaf(v.w, c, agg.w);
        }
        __syncthreads();
    }
    const float4 bb = *(const float4*)(bias + t * 4);
    float4 r;
    r.x = fmaxf(hself.x / deg + dinv_d * agg.x + bb.x, 0.0f);
    r.y = fmaxf(hself.y / deg + dinv_d * agg.y + bb.y, 0.0f);
    r.z = fmaxf(hself.z / deg + dinv_d * agg.z + bb.z, 0.0f);
    r.w = fmaxf(hself.w / deg + dinv_d * agg.w + bb.w, 0.0f);
    *(float4*)(out + (size_t)row * NHID + t * 4) = r;

    const float4 w = *(const float4*)(Wp + t * 4);
    float p = r.x * w.x + r.y * w.y + r.z * w.z + r.w * w.w;
#pragma unroll
    for (int o = 16; o > 0; o >>= 1) p += __shfl_down_sync(0xffffffffu, p, o);
    if ((t & 31) == 0) red[t >> 5] = p;
    __syncthreads();
    if (t == 0) g_s0[row] = red[0] + red[1] + red[2] + red[3];
}

// ---------------- score gather ----------------
__global__ void k_score(const float* __restrict__ bp, int n) {
    int row = blockIdx.x * 8 + (threadIdx.x >> 5);
    if (row >= BATCH * n) return;
    int lane = threadIdx.x & 31;
    int b = row / n, bn = b * n;
    int start = g_rowstart[row];
    int cnt = g_cnt[row];
    float sum = 0.0f;
    for (int e = lane; e < cnt; e += 32) {
        int s = g_csr[b * NEDGE + start + e];
        sum += g_s0[bn + s] * rsqrtf((float)(g_cnt[bn + s] + 1));
    }
#pragma unroll
    for (int o = 16; o > 0; o >>= 1) sum += __shfl_down_sync(0xffffffffu, sum, o);
    if (lane == 0) {
        float deg = (float)(cnt + 1);
        g_score[row] = g_s0[row] / deg + rsqrtf(deg) * sum + bp[0];
    }
}

// ---------------- top-k: per-batch bitonic sort ----------------
__global__ void k_topk(int n, int k) {
    extern __shared__ char sm[];
    float* sv = (float*)sm;
    int* si = (int*)(sv + n);
    int b = blockIdx.x, tid = threadIdx.x;
    for (int i = tid; i < n; i += blockDim.x) { sv[i] = g_score[b * n + i]; si[i] = i; }
    __syncthreads();
    for (int ksz = 2; ksz <= n; ksz <<= 1) {
        for (int j = ksz >> 1; j > 0; j >>= 1) {
            for (int i = tid; i < n; i += blockDim.x) {
                int ixj = i ^ j;
                if (ixj > i) {
                    float v1 = sv[i], v2 = sv[ixj];
                    int i1 = si[i], i2 = si[ixj];
                    bool before = (v1 > v2) || (v1 == v2 && i1 < i2);
                    bool desc = ((i & ksz) == 0);
                    if (desc ? !before : before) {
                        sv[i] = v2; sv[ixj] = v1; si[i] = i2; si[ixj] = i1;
                    }
                }
            }
            __syncthreads();
        }
    }
    for (int i = tid; i < n; i += blockDim.x) g_newidx[b * n + i] = -1;
    __syncthreads();
    for (int t = tid; t < k; t += blockDim.x) {
        int p = si[t];
        g_perm[b * n + t] = p;
        g_newidx[b * n + p] = t;
    }
}

// ---------------- fused pool + readout + bf16 split (no fp32 xk buffer) ----------------
__global__ __launch_bounds__(128) void k_pool_readout(const float* __restrict__ h,
                                                      __nv_bfloat16* __restrict__ hi,
                                                      __nv_bfloat16* __restrict__ lo,
                                                      int n, int k) {
    __shared__ float tv[1024];
    __shared__ int   pp[1024];
    const int b = blockIdx.x, fc = blockIdx.y, t = threadIdx.x;
    for (int r = t; r < k; r += 128) {
        int p = g_perm[b * n + r];
        pp[r] = p;
        tv[r] = tanhf(g_score[b * n + p]);
    }
    __syncthreads();
    const int f = fc * 128 + t;
    float mx = -INFINITY, sm = 0.0f;
    if (hi) {
        for (int r = 0; r < k; r++) {
            float v = h[((size_t)b * n + pp[r]) * NHID + f] * tv[r];
            mx = fmaxf(mx, v);
            sm += v;
            size_t o = ((size_t)b * k + r) * NHID + f;
            __nv_bfloat16 vh = __float2bfloat16(v);
            hi[o] = vh;
            lo[o] = __float2bfloat16(v - __bfloat162float(vh));
        }
    } else {
        for (int r = 0; r < k; r++) {
            float v = h[((size_t)b * n + pp[r]) * NHID + f] * tv[r];
            mx = fmaxf(mx, v);
            sm += v;
        }
    }
    g_z[b * 1024 + f] += mx;
    g_z[b * 1024 + 512 + f] += sm / (float)k;
}

// ---------------- edge relabel + count for next stage (fused) ----------------
__global__ void k_edge_update_count(int n, int k) {
    int i = blockIdx.x * blockDim.x + threadIdx.x;
    if (i >= BATCH * NEDGE) return;
    int b = i / NEDGE;
    if (g_em[i] != 0.0f) {
        int ns = g_newidx[b * n + g_src[i]];
        int nd = g_newidx[b * n + g_dst[i]];
        if (ns >= 0 && nd >= 0) {
            g_src[i] = ns; g_dst[i] = nd;
            atomicAdd(&g_cnt[b * k + nd], 1);
        } else { g_em[i] = 0.0f; g_src[i] = 0; g_dst[i] = 0; }
    } else { g_src[i] = 0; g_dst[i] = 0; }
}

// ---------------- head ----------------
__global__ void k_head(const float* __restrict__ l1W, const float* __restrict__ l1b,
                       const float* __restrict__ l2W, const float* __restrict__ l2b,
                       const float* __restrict__ piW, const float* __restrict__ pib,
                       const float* __restrict__ vW, const float* __restrict__ vb,
                       float* __restrict__ out) {
    __shared__ float zz[1024];
    __shared__ float z1[512];
    __shared__ float z2[256];
    __shared__ float lg[128];
    __shared__ float stats[2];
    int b = blockIdx.x, tid = threadIdx.x;
    for (int i = tid; i < 1024; i += 256) zz[i] = g_z[b * 1024 + i];
    __syncthreads();
    for (int j = tid; j < 512; j += 256) {
        float a = l1b[j];
        for (int i = 0; i < 1024; i++) a = fmaf(zz[i], l1W[i * 512 + j], a);
        z1[j] = fmaxf(a, 0.0f);
    }
    __syncthreads();
    {
        int j = tid;
        float a = l2b[j];
        for (int i = 0; i < 512; i++) a = fmaf(z1[i], l2W[i * 256 + j], a);
        z2[j] = fmaxf(a, 0.0f);
    }
    __syncthreads();
    if (tid < 128) {
        float a = pib[tid];
        for (int i = 0; i < 256; i++) a = fmaf(z2[i], piW[i * 128 + tid], a);
        lg[tid] = a;
    } else if (tid == 128) {
        float a = vb[0];
        for (int i = 0; i < 256; i++) a = fmaf(z2[i], vW[i], a);
        out[BATCH * RULES + b] = fmaxf(a, 0.0f);
    }
    __syncthreads();
    if (tid == 0) {
        float mx = -INFINITY;
        for (int i = 0; i < 128; i++) mx = fmaxf(mx, lg[i]);
        float s = 0.0f;
        for (int i = 0; i < 128; i++) s += expf(lg[i] - mx);
        stats[0] = mx;
        stats[1] = logf(s);
    }
    __syncthreads();
    if (tid < 128) out[b * RULES + tid] = lg[tid] - stats[0] - stats[1];
}

// ---------------- host orchestration ----------------
static void run_stage(float* h0buf, float* gout,
                      __nv_bfloat16* ahi, __nv_bfloat16* alo,
                      __nv_bfloat16* whi, __nv_bfloat16* wlo,
                      int n, int k, int K,
                      const float* W, const float* bias,
                      const float* Wp, const float* bp, bool relabel,
                      bool split_next) {
    const int EB = BATCH * NEDGE;
    k_scan_fill<<<BATCH, 1024>>>(n);
    k_split_w<<<(512 * K + 255) / 256, 256>>>(W, whi, wlo, K);
    k_gemm_mma<<<dim3(2, (BATCH * n) / 128), 512, GEMM_SMEM>>>(ahi, alo, whi, wlo, h0buf,
                                                               BATCH * n, K);
    k_gather<<<BATCH * n, 128>>>(h0buf, gout, bias, Wp, n);
    k_score<<<(BATCH * n) / 8, 256>>>(bp, n);
    k_topk<<<BATCH, 1024, n * 8>>>(n, k);
    k_pool_readout<<<dim3(BATCH, 4), 128>>>(
        gout, split_next ? ahi : (__nv_bfloat16*)nullptr,
        split_next ? alo : (__nv_bfloat16*)nullptr, n, k);
    if (relabel) {
        k_zero_cnt<<<(BATCH * k + 255) / 256, 256>>>(BATCH * k);
        k_edge_update_count<<<(EB + 255) / 256, 256>>>(n, k);
    }
}

extern "C" void kernel_launch(void* const* d_in, const int* in_sizes, int n_in,
                              void* d_out, int out_size) {
    const float* x    = (const float*)d_in[0];
    const int*   src  = (const int*)d_in[1];
    const int*   dst  = (const int*)d_in[2];
    const float* W1   = (const float*)d_in[3];
    const float* b1   = (const float*)d_in[4];
    const float* Wp1  = (const float*)d_in[5];
    const float* bp1  = (const float*)d_in[6];
    const float* W2   = (const float*)d_in[7];
    const float* b2   = (const float*)d_in[8];
    const float* Wp2  = (const float*)d_in[9];
    const float* bp2  = (const float*)d_in[10];
    const float* W3   = (const float*)d_in[11];
    const float* b3   = (const float*)d_in[12];
    const float* Wp3  = (const float*)d_in[13];
    const float* bp3  = (const float*)d_in[14];
    const float* l1W  = (const float*)d_in[15];
    const float* l1b  = (const float*)d_in[16];
    const float* l2W  = (const float*)d_in[17];
    const float* l2b  = (const float*)d_in[18];
    const float* piW  = (const float*)d_in[19];
    const float* pib  = (const float*)d_in[20];
    const float* vW   = (const float*)d_in[21];
    const float* vb   = (const float*)d_in[22];
    float* out = (float*)d_out;

    float *pA = nullptr, *pB = nullptr;
    __nv_bfloat16 *ahi = nullptr, *alo = nullptr, *whi = nullptr, *wlo = nullptr;
    cudaGetSymbolAddress((void**)&pA, g_bufA);
    cudaGetSymbolAddress((void**)&pB, g_bufB);
    cudaGetSymbolAddress((void**)&ahi, g_ahi);
    cudaGetSymbolAddress((void**)&alo, g_alo);
    cudaGetSymbolAddress((void**)&whi, g_whi);
    cudaGetSymbolAddress((void**)&wlo, g_wlo);

    cudaFuncSetAttribute(k_gemm_mma, cudaFuncAttributeMaxDynamicSharedMemorySize, GEMM_SMEM);

    k_zero_cnt<<<(BATCH * NMAX + 255) / 256, 256>>>(BATCH * NMAX);
    k_init_edges_count<<<(BATCH * NEDGE + 255) / 256, 256>>>(src, dst);
    k_zero_z<<<(BATCH * 2 * NHID + 255) / 256, 256>>>();
    k_split_a<<<(int)(((size_t)BATCH * NMAX * FIN + 255) / 256), 256>>>(
        x, ahi, alo, (size_t)BATCH * NMAX * FIN);

    // stage 1: 2048 nodes, K=256 -> h0=A, gcn=B, pool(split) -> ahi/alo (1024 nodes)
    run_stage(pA, pB, ahi, alo, whi, wlo, 2048, 1024, FIN,  W1, b1, Wp1, bp1, true,  true);
    // stage 2: 1024 nodes -> h0=A, gcn=B, pool(split) -> ahi/alo (512 nodes)
    run_stage(pA, pB, ahi, alo, whi, wlo, 1024, 512,  NHID, W2, b2, Wp2, bp2, true,  true);
    // stage 3: 512 nodes -> h0=A, gcn=B, readout only
    run_stage(pA, pB, ahi, alo, whi, wlo, 512,  256,  NHID, W3, b3, Wp3, bp3, false, false);

    k_head<<<BATCH, 256>>>(l1W, l1b, l2W, l2b, piW, pib, vW, vb, out);
}

// round 8
// speedup vs baseline: 3.1451x; 1.0064x over previous
#include <cuda_runtime.h>
#include <cuda_bf16.h>
#include <math.h>
#include <stdint.h>

#define BATCH 64
#define NMAX  2048
#define NEDGE 32768
#define FIN   256
#define NHID  512
#define RULES 128

// ---------------- scratch (device globals; no allocations) ----------------
static __device__ float g_bufA[(size_t)BATCH * NMAX * NHID];   // 256 MB
static __device__ float g_bufB[(size_t)BATCH * NMAX * NHID];   // 256 MB
static __device__ __align__(16) __nv_bfloat16 g_ahi[(size_t)BATCH * NMAX * NHID / 2];
static __device__ __align__(16) __nv_bfloat16 g_alo[(size_t)BATCH * NMAX * NHID / 2];
static __device__ __align__(16) __nv_bfloat16 g_whi[NHID * NHID];
static __device__ __align__(16) __nv_bfloat16 g_wlo[NHID * NHID];
static __device__ int   g_cnt[BATCH * NMAX];
static __device__ int   g_rowstart[BATCH * NMAX];
static __device__ int   g_csr[BATCH * NEDGE];
static __device__ float g_s0[BATCH * NMAX];
static __device__ float g_score[BATCH * NMAX];
static __device__ int   g_perm[BATCH * NMAX];
static __device__ int   g_newidx[BATCH * NMAX];
static __device__ int   g_src[BATCH * NEDGE];
static __device__ int   g_dst[BATCH * NEDGE];
static __device__ float g_em[BATCH * NEDGE];
static __device__ float g_z[BATCH * 2 * NHID];

// ---------------- helpers ----------------
__device__ __forceinline__ uint32_t smem_u32(const void* p) {
    uint32_t a;
    asm("{ .reg .u64 t; cvta.to.shared.u64 t, %1; cvt.u32.u64 %0, t; }" : "=r"(a) : "l"(p));
    return a;
}
__device__ __forceinline__ void cp16(uint32_t saddr, const void* gptr) {
    asm volatile("cp.async.cg.shared.global [%0], [%1], 16;"
                 :: "r"(saddr), "l"(__cvta_generic_to_global(gptr)) : "memory");
}
__device__ __forceinline__ void ldsm4(uint32_t& r0, uint32_t& r1, uint32_t& r2, uint32_t& r3,
                                      uint32_t addr) {
    asm volatile("ldmatrix.sync.aligned.m8n8.x4.shared.b16 {%0,%1,%2,%3}, [%4];"
                 : "=r"(r0), "=r"(r1), "=r"(r2), "=r"(r3) : "r"(addr));
}
__device__ __forceinline__ void mma_bf16(float* c, uint32_t a0, uint32_t a1, uint32_t a2,
                                         uint32_t a3, uint32_t b0, uint32_t b1) {
    asm volatile(
        "mma.sync.aligned.m16n8k16.row.col.f32.bf16.bf16.f32 "
        "{%0,%1,%2,%3}, {%4,%5,%6,%7}, {%8,%9}, {%0,%1,%2,%3};"
        : "+f"(c[0]), "+f"(c[1]), "+f"(c[2]), "+f"(c[3])
        : "r"(a0), "r"(a1), "r"(a2), "r"(a3), "r"(b0), "r"(b1));
}
__device__ __forceinline__ uint32_t pk2(float a, float b) {
    __nv_bfloat162 t = __floats2bfloat162_rn(a, b);
    return *(uint32_t*)&t;
}

// ---------------- init (stage-1 count fused in) ----------------
__global__ void k_zero_cnt(int total) {
    int i = blockIdx.x * blockDim.x + threadIdx.x;
    if (i < total) g_cnt[i] = 0;
}
__global__ void k_init_edges_count(const int* __restrict__ src, const int* __restrict__ dst) {
    int i = blockIdx.x * blockDim.x + threadIdx.x;
    if (i >= BATCH * NEDGE) return;
    int s = src[i], d = dst[i];
    g_src[i] = s; g_dst[i] = d; g_em[i] = 1.0f;
    int b = i / NEDGE;
    atomicAdd(&g_cnt[b * NMAX + d], 1);
}
__global__ void k_zero_z() {
    int i = blockIdx.x * blockDim.x + threadIdx.x;
    if (i < BATCH * 2 * NHID) g_z[i] = 0.0f;
}

// ---------------- fused per-batch scan + CSR fill (shared-mem cursors) ----------------
__global__ __launch_bounds__(1024) void k_scan_fill(int n) {
    __shared__ int buf[2][NMAX];
    __shared__ int cur[NMAX];
    int b = blockIdx.x, tid = threadIdx.x;
    for (int i = tid; i < n; i += 1024) buf[0][i] = g_cnt[b * n + i];
    __syncthreads();
    int s = 0;
    for (int d = 1; d < n; d <<= 1) {
        for (int i = tid; i < n; i += 1024) {
            int v = buf[s][i];
            if (i >= d) v += buf[s][i - d];
            buf[s ^ 1][i] = v;
        }
        __syncthreads();
        s ^= 1;
    }
    for (int i = tid; i < n; i += 1024) {
        int excl = (i == 0) ? 0 : buf[s][i - 1];
        g_rowstart[b * n + i] = excl;
        cur[i] = excl;
    }
    __syncthreads();
    for (int e = tid; e < NEDGE; e += 1024) {
        int i = b * NEDGE + e;
        if (g_em[i] != 0.0f) {
            int pos = atomicAdd(&cur[g_dst[i]], 1);
            g_csr[b * NEDGE + pos] = g_src[i];
        }
    }
}

// ---------------- fp32 -> bf16 split, vectorized (8 elems/thread) ----------------
__global__ void k_split_a8(const float4* __restrict__ in, uint4* __restrict__ hi,
                           uint4* __restrict__ lo, size_t total8) {
    size_t i = (size_t)blockIdx.x * blockDim.x + threadIdx.x;
    if (i >= total8) return;
    float4 v0 = in[2 * i], v1 = in[2 * i + 1];
    float h[8], l[8];
    float vv[8] = {v0.x, v0.y, v0.z, v0.w, v1.x, v1.y, v1.z, v1.w};
#pragma unroll
    for (int j = 0; j < 8; j++) {
        h[j] = __bfloat162float(__float2bfloat16(vv[j]));
        l[j] = vv[j] - h[j];
    }
    hi[i] = make_uint4(pk2(vv[0], vv[1]), pk2(vv[2], vv[3]), pk2(vv[4], vv[5]), pk2(vv[6], vv[7]));
    lo[i] = make_uint4(pk2(l[0], l[1]), pk2(l[2], l[3]), pk2(l[4], l[5]), pk2(l[6], l[7]));
}

// ---------------- weight split + transpose via smem tile ----------------
// W[K,512] -> Wt split [512,K]; grid (K/32, 16), block (32,8)
__global__ void k_split_w(const float* __restrict__ W, __nv_bfloat16* __restrict__ hi,
                          __nv_bfloat16* __restrict__ lo, int K) {
    __shared__ float tile[32][33];
    const int k0 = blockIdx.x * 32, n0 = blockIdx.y * 32;
    const int tx = threadIdx.x, ty = threadIdx.y;
#pragma unroll
    for (int j = 0; j < 4; j++) {
        int kr = ty + j * 8;
        tile[kr][tx] = W[(size_t)(k0 + kr) * 512 + n0 + tx];
    }
    __syncthreads();
#pragma unroll
    for (int j = 0; j < 4; j++) {
        int nr = ty + j * 8;
        float v = tile[tx][nr];
        __nv_bfloat16 h = __float2bfloat16(v);
        size_t o = (size_t)(n0 + nr) * K + k0 + tx;
        hi[o] = h;
        lo[o] = __float2bfloat16(v - __bfloat162float(h));
    }
}

// ---------------- split-bf16 tensor GEMM via mma.sync (3-stage pipeline) ----------------
// C[M,512] = A[M,K] @ W[K,512].  C = Ahi@Bhi + Ahi@Blo + Alo@Bhi  (f32 accum).
// CTA: 128x256 tile, BK=32, 512 threads / 16 warps (warp_m 0..3 x warp_n 0..3, 32x64 each).
#define LDS_E   40                          // row stride elems (80 B, conflict-free phases)
#define TILE_A  (128 * LDS_E * 2)           // 10240 B
#define TILE_BS (256 * LDS_E * 2)           // 20480 B
#define STAGE_B (2 * TILE_A + 2 * TILE_BS)  // 61440 B
#define GEMM_SMEM (3 * STAGE_B)             // 184320 B
__global__ __launch_bounds__(512, 1) void k_gemm_mma(
    const __nv_bfloat16* __restrict__ Ahi, const __nv_bfloat16* __restrict__ Alo,
    const __nv_bfloat16* __restrict__ Bhi, const __nv_bfloat16* __restrict__ Blo,
    float* __restrict__ C, int M, int K)
{
    extern __shared__ __align__(128) char smem[];
    const uint32_t sb = smem_u32(smem);
    const int tid = threadIdx.x;
    const int wid = tid >> 5;
    const int lane = tid & 31;
    const int warp_m = wid & 3;
    const int warp_n = wid >> 2;
    const int rowBase = blockIdx.y * 128;
    const int colBase = blockIdx.x * 256;

    const int g = lane >> 3;
    const int a_m = lane & 15;
    const int a_k = (lane >> 4) << 3;
    const int b_n = lane - ((g == 0) ? 0 : (g == 3) ? 16 : 8);
    const int b_k = (g & 1) << 3;

    uint32_t aoff[2], boff[4];
#pragma unroll
    for (int mt = 0; mt < 2; mt++)
        aoff[mt] = ((warp_m * 32 + mt * 16 + a_m) * LDS_E + a_k) * 2;
#pragma unroll
    for (int ng = 0; ng < 4; ng++)
        boff[ng] = ((warp_n * 64 + ng * 16 + b_n) * LDS_E + b_k) * 2;

    float acc[2][8][4];
#pragma unroll
    for (int mt = 0; mt < 2; mt++)
#pragma unroll
        for (int nf = 0; nf < 8; nf++)
#pragma unroll
            for (int e = 0; e < 4; e++) acc[mt][nf][e] = 0.0f;

    const int nch = K >> 5;

    auto load_stage = [&](int t) {
        const uint32_t base = sb + (t % 3) * STAGE_B;
        const int kc0 = t << 5;
        {
            int r = tid >> 2, blk = tid & 3;
            uint32_t so = r * (LDS_E * 2) + blk * 16;
            size_t ga = (size_t)(rowBase + r) * K + kc0 + blk * 8;
            cp16(base + so,          Ahi + ga);
            cp16(base + TILE_A + so, Alo + ga);
        }
#pragma unroll
        for (int part = 0; part < 2; part++) {
            int idx = tid + part * 512;
            int r = idx >> 2, blk = idx & 3;
            uint32_t so = r * (LDS_E * 2) + blk * 16;
            size_t gb = (size_t)(colBase + r) * K + kc0 + blk * 8;
            cp16(base + 2 * TILE_A + so,           Bhi + gb);
            cp16(base + 2 * TILE_A + TILE_BS + so, Blo + gb);
        }
        asm volatile("cp.async.commit_group;" ::: "memory");
    };

    load_stage(0);
    if (nch > 1) load_stage(1);
    for (int t = 0; t < nch; t++) {
        if (t + 2 < nch) {
            load_stage(t + 2);
            asm volatile("cp.async.wait_group 2;" ::: "memory");
        } else if (t + 1 < nch) {
            asm volatile("cp.async.wait_group 1;" ::: "memory");
        } else {
            asm volatile("cp.async.wait_group 0;" ::: "memory");
        }
        __syncthreads();
        const uint32_t base = sb + (t % 3) * STAGE_B;
        const uint32_t bbase = base + 2 * TILE_A;
#pragma unroll
        for (int kk = 0; kk < 2; kk++) {
            const uint32_t ko = kk * 32;
            uint32_t ah[2][4], al[2][4];
#pragma unroll
            for (int mt = 0; mt < 2; mt++) {
                ldsm4(ah[mt][0], ah[mt][1], ah[mt][2], ah[mt][3], base + aoff[mt] + ko);
                ldsm4(al[mt][0], al[mt][1], al[mt][2], al[mt][3], base + TILE_A + aoff[mt] + ko);
            }
#pragma unroll
            for (int half = 0; half < 2; half++) {
                uint32_t bh[4][2], bl[4][2];
#pragma unroll
                for (int gg = 0; gg < 2; gg++) {
                    int ng = half * 2 + gg;
                    uint32_t r0, r1, r2, r3;
                    ldsm4(r0, r1, r2, r3, bbase + boff[ng] + ko);
                    bh[gg * 2][0] = r0; bh[gg * 2][1] = r1;
                    bh[gg * 2 + 1][0] = r2; bh[gg * 2 + 1][1] = r3;
                    ldsm4(r0, r1, r2, r3, bbase + TILE_BS + boff[ng] + ko);
                    bl[gg * 2][0] = r0; bl[gg * 2][1] = r1;
                    bl[gg * 2 + 1][0] = r2; bl[gg * 2 + 1][1] = r3;
                }
#pragma unroll
                for (int mt = 0; mt < 2; mt++)
#pragma unroll
                    for (int q = 0; q < 4; q++) {
                        int nf = half * 4 + q;
                        mma_bf16(acc[mt][nf], ah[mt][0], ah[mt][1], ah[mt][2], ah[mt][3],
                                 bh[q][0], bh[q][1]);
                        mma_bf16(acc[mt][nf], ah[mt][0], ah[mt][1], ah[mt][2], ah[mt][3],
                                 bl[q][0], bl[q][1]);
                        mma_bf16(acc[mt][nf], al[mt][0], al[mt][1], al[mt][2], al[mt][3],
                                 bh[q][0], bh[q][1]);
                    }
            }
        }
        __syncthreads();
    }

#pragma unroll
    for (int mt = 0; mt < 2; mt++) {
        int r0 = rowBase + warp_m * 32 + mt * 16 + (lane >> 2);
        int r1 = r0 + 8;
#pragma unroll
        for (int nf = 0; nf < 8; nf++) {
            int col = colBase + warp_n * 64 + nf * 8 + (lane & 3) * 2;
            *(float2*)(C + (size_t)r0 * 512 + col) = make_float2(acc[mt][nf][0], acc[mt][nf][1]);
            *(float2*)(C + (size_t)r1 * 512 + col) = make_float2(acc[mt][nf][2], acc[mt][nf][3]);
        }
    }
}

// ---------------- fused GCN gather + self + bias + relu + scorer dot ----------------
__global__ __launch_bounds__(128) void k_gather(const float* __restrict__ h0,
                                                float* __restrict__ out,
                                                const float* __restrict__ bias,
                                                const float* __restrict__ Wp, int n) {
    __shared__ int   nb[128];
    __shared__ float cf[128];
    __shared__ float red[4];
    const int row = blockIdx.x;
    const int b = row / n;
    const int bn = b * n;
    const int t = threadIdx.x;
    const int start = g_rowstart[row];
    const int cnt = g_cnt[row];
    const float deg = (float)(cnt + 1);
    const float dinv_d = rsqrtf(deg);

    const float4 hself = *(const float4*)(h0 + (size_t)row * NHID + t * 4);
    float4 agg = make_float4(0.f, 0.f, 0.f, 0.f);

    for (int base = 0; base < cnt; base += 128) {
        int m = min(128, cnt - base);
        if (t < m) {
            int s = g_csr[b * NEDGE + start + base + t];
            nb[t] = s;
            cf[t] = rsqrtf((float)(g_cnt[bn + s] + 1));
        }
        __syncthreads();
#pragma unroll 8
        for (int e = 0; e < m; e++) {
            const float c = cf[e];
            const float4 v = *(const float4*)(h0 + ((size_t)bn + nb[e]) * NHID + t * 4);
            agg.x = fmaf(v.x, c, agg.x);
            agg.y = fmaf(v.y, c, agg.y);
            agg.z = fmaf(v.z, c, agg.z);
            agg.w = fmaf(v.w, c, agg.w);
        }
        __syncthreads();
    }
    const float4 bb = *(const float4*)(bias + t * 4);
    float4 r;
    r.x = fmaxf(hself.x / deg + dinv_d * agg.x + bb.x, 0.0f);
    r.y = fmaxf(hself.y / deg + dinv_d * agg.y + bb.y, 0.0f);
    r.z = fmaxf(hself.z / deg + dinv_d * agg.z + bb.z, 0.0f);
    r.w = fmaxf(hself.w / deg + dinv_d * agg.w + bb.w, 0.0f);
    *(float4*)(out + (size_t)row * NHID + t * 4) = r;

    const float4 w = *(const float4*)(Wp + t * 4);
    float p = r.x * w.x + r.y * w.y + r.z * w.z + r.w * w.w;
#pragma unroll
    for (int o = 16; o > 0; o >>= 1) p += __shfl_down_sync(0xffffffffu, p, o);
    if ((t & 31) == 0) red[t >> 5] = p;
    __syncthreads();
    if (t == 0) g_s0[row] = red[0] + red[1] + red[2] + red[3];
}

// ---------------- score gather ----------------
__global__ void k_score(const float* __restrict__ bp, int n) {
    int row = blockIdx.x * 8 + (threadIdx.x >> 5);
    if (row >= BATCH * n) return;
    int lane = threadIdx.x & 31;
    int b = row / n, bn = b * n;
    int start = g_rowstart[row];
    int cnt = g_cnt[row];
    float sum = 0.0f;
    for (int e = lane; e < cnt; e += 32) {
        int s = g_csr[b * NEDGE + start + e];
        sum += g_s0[bn + s] * rsqrtf((float)(g_cnt[bn + s] + 1));
    }
#pragma unroll
    for (int o = 16; o > 0; o >>= 1) sum += __shfl_down_sync(0xffffffffu, sum, o);
    if (lane == 0) {
        float deg = (float)(cnt + 1);
        g_score[row] = g_s0[row] / deg + rsqrtf(deg) * sum + bp[0];
    }
}

// ---------------- top-k: per-batch bitonic sort ----------------
__global__ void k_topk(int n, int k) {
    extern __shared__ char sm[];
    float* sv = (float*)sm;
    int* si = (int*)(sv + n);
    int b = blockIdx.x, tid = threadIdx.x;
    for (int i = tid; i < n; i += blockDim.x) { sv[i] = g_score[b * n + i]; si[i] = i; }
    __syncthreads();
    for (int ksz = 2; ksz <= n; ksz <<= 1) {
        for (int j = ksz >> 1; j > 0; j >>= 1) {
            for (int i = tid; i < n; i += blockDim.x) {
                int ixj = i ^ j;
                if (ixj > i) {
                    float v1 = sv[i], v2 = sv[ixj];
                    int i1 = si[i], i2 = si[ixj];
                    bool before = (v1 > v2) || (v1 == v2 && i1 < i2);
                    bool desc = ((i & ksz) == 0);
                    if (desc ? !before : before) {
                        sv[i] = v2; sv[ixj] = v1; si[i] = i2; si[ixj] = i1;
                    }
                }
            }
            __syncthreads();
        }
    }
    for (int i = tid; i < n; i += blockDim.x) g_newidx[b * n + i] = -1;
    __syncthreads();
    for (int t = tid; t < k; t += blockDim.x) {
        int p = si[t];
        g_perm[b * n + t] = p;
        g_newidx[b * n + p] = t;
    }
}

// ---------------- fused pool + readout + bf16 split ----------------
__global__ __launch_bounds__(128) void k_pool_readout(const float* __restrict__ h,
                                                      __nv_bfloat16* __restrict__ hi,
                                                      __nv_bfloat16* __restrict__ lo,
                                                      int n, int k) {
    __shared__ float tv[1024];
    __shared__ int   pp[1024];
    const int b = blockIdx.x, fc = blockIdx.y, t = threadIdx.x;
    for (int r = t; r < k; r += 128) {
        int p = g_perm[b * n + r];
        pp[r] = p;
        tv[r] = tanhf(g_score[b * n + p]);
    }
    __syncthreads();
    const int f = fc * 128 + t;
    float mx = -INFINITY, sm = 0.0f;
    if (hi) {
        for (int r = 0; r < k; r++) {
            float v = h[((size_t)b * n + pp[r]) * NHID + f] * tv[r];
            mx = fmaxf(mx, v);
            sm += v;
            size_t o = ((size_t)b * k + r) * NHID + f;
            __nv_bfloat16 vh = __float2bfloat16(v);
            hi[o] = vh;
            lo[o] = __float2bfloat16(v - __bfloat162float(vh));
        }
    } else {
        for (int r = 0; r < k; r++) {
            float v = h[((size_t)b * n + pp[r]) * NHID + f] * tv[r];
            mx = fmaxf(mx, v);
            sm += v;
        }
    }
    g_z[b * 1024 + f] += mx;
    g_z[b * 1024 + 512 + f] += sm / (float)k;
}

// ---------------- edge relabel + count for next stage (fused) ----------------
__global__ void k_edge_update_count(int n, int k) {
    int i = blockIdx.x * blockDim.x + threadIdx.x;
    if (i >= BATCH * NEDGE) return;
    int b = i / NEDGE;
    if (g_em[i] != 0.0f) {
        int ns = g_newidx[b * n + g_src[i]];
        int nd = g_newidx[b * n + g_dst[i]];
        if (ns >= 0 && nd >= 0) {
            g_src[i] = ns; g_dst[i] = nd;
            atomicAdd(&g_cnt[b * k + nd], 1);
        } else { g_em[i] = 0.0f; g_src[i] = 0; g_dst[i] = 0; }
    } else { g_src[i] = 0; g_dst[i] = 0; }
}

// ---------------- head ----------------
__global__ void k_head(const float* __restrict__ l1W, const float* __restrict__ l1b,
                       const float* __restrict__ l2W, const float* __restrict__ l2b,
                       const float* __restrict__ piW, const float* __restrict__ pib,
                       const float* __restrict__ vW, const float* __restrict__ vb,
                       float* __restrict__ out) {
    __shared__ float zz[1024];
    __shared__ float z1[512];
    __shared__ float z2[256];
    __shared__ float lg[128];
    __shared__ float stats[2];
    int b = blockIdx.x, tid = threadIdx.x;
    for (int i = tid; i < 1024; i += 256) zz[i] = g_z[b * 1024 + i];
    __syncthreads();
    for (int j = tid; j < 512; j += 256) {
        float a = l1b[j];
        for (int i = 0; i < 1024; i++) a = fmaf(zz[i], l1W[i * 512 + j], a);
        z1[j] = fmaxf(a, 0.0f);
    }
    __syncthreads();
    {
        int j = tid;
        float a = l2b[j];
        for (int i = 0; i < 512; i++) a = fmaf(z1[i], l2W[i * 256 + j], a);
        z2[j] = fmaxf(a, 0.0f);
    }
    __syncthreads();
    if (tid < 128) {
        float a = pib[tid];
        for (int i = 0; i < 256; i++) a = fmaf(z2[i], piW[i * 128 + tid], a);
        lg[tid] = a;
    } else if (tid == 128) {
        float a = vb[0];
        for (int i = 0; i < 256; i++) a = fmaf(z2[i], vW[i], a);
        out[BATCH * RULES + b] = fmaxf(a, 0.0f);
    }
    __syncthreads();
    if (tid == 0) {
        float mx = -INFINITY;
        for (int i = 0; i < 128; i++) mx = fmaxf(mx, lg[i]);
        float s = 0.0f;
        for (int i = 0; i < 128; i++) s += expf(lg[i] - mx);
        stats[0] = mx;
        stats[1] = logf(s);
    }
    __syncthreads();
    if (tid < 128) out[b * RULES + tid] = lg[tid] - stats[0] - stats[1];
}

// ---------------- host orchestration ----------------
static void run_stage(float* h0buf, float* gout,
                      __nv_bfloat16* ahi, __nv_bfloat16* alo,
                      __nv_bfloat16* whi, __nv_bfloat16* wlo,
                      int n, int k, int K,
                      const float* W, const float* bias,
                      const float* Wp, const float* bp, bool relabel,
                      bool split_next) {
    const int EB = BATCH * NEDGE;
    k_scan_fill<<<BATCH, 1024>>>(n);
    k_split_w<<<dim3(K / 32, 16), dim3(32, 8)>>>(W, whi, wlo, K);
    k_gemm_mma<<<dim3(2, (BATCH * n) / 128), 512, GEMM_SMEM>>>(ahi, alo, whi, wlo, h0buf,
                                                               BATCH * n, K);
    k_gather<<<BATCH * n, 128>>>(h0buf, gout, bias, Wp, n);
    k_score<<<(BATCH * n) / 8, 256>>>(bp, n);
    k_topk<<<BATCH, 1024, n * 8>>>(n, k);
    k_pool_readout<<<dim3(BATCH, 4), 128>>>(
        gout, split_next ? ahi : (__nv_bfloat16*)nullptr,
        split_next ? alo : (__nv_bfloat16*)nullptr, n, k);
    if (relabel) {
        k_zero_cnt<<<(BATCH * k + 255) / 256, 256>>>(BATCH * k);
        k_edge_update_count<<<(EB + 255) / 256, 256>>>(n, k);
    }
}

extern "C" void kernel_launch(void* const* d_in, const int* in_sizes, int n_in,
                              void* d_out, int out_size) {
    const float* x    = (const float*)d_in[0];
    const int*   src  = (const int*)d_in[1];
    const int*   dst  = (const int*)d_in[2];
    const float* W1   = (const float*)d_in[3];
    const float* b1   = (const float*)d_in[4];
    const float* Wp1  = (const float*)d_in[5];
    const float* bp1  = (const float*)d_in[6];
    const float* W2   = (const float*)d_in[7];
    const float* b2   = (const float*)d_in[8];
    const float* Wp2  = (const float*)d_in[9];
    const float* bp2  = (const float*)d_in[10];
    const float* W3   = (const float*)d_in[11];
    const float* b3   = (const float*)d_in[12];
    const float* Wp3  = (const float*)d_in[13];
    const float* bp3  = (const float*)d_in[14];
    const float* l1W  = (const float*)d_in[15];
    const float* l1b  = (const float*)d_in[16];
    const float* l2W  = (const float*)d_in[17];
    const float* l2b  = (const float*)d_in[18];
    const float* piW  = (const float*)d_in[19];
    const float* pib  = (const float*)d_in[20];
    const float* vW   = (const float*)d_in[21];
    const float* vb   = (const float*)d_in[22];
    float* out = (float*)d_out;

    float *pA = nullptr, *pB = nullptr;
    __nv_bfloat16 *ahi = nullptr, *alo = nullptr, *whi = nullptr, *wlo = nullptr;
    cudaGetSymbolAddress((void**)&pA, g_bufA);
    cudaGetSymbolAddress((void**)&pB, g_bufB);
    cudaGetSymbolAddress((void**)&ahi, g_ahi);
    cudaGetSymbolAddress((void**)&alo, g_alo);
    cudaGetSymbolAddress((void**)&whi, g_whi);
    cudaGetSymbolAddress((void**)&wlo, g_wlo);

    cudaFuncSetAttribute(k_gemm_mma, cudaFuncAttributeMaxDynamicSharedMemorySize, GEMM_SMEM);

    k_zero_cnt<<<(BATCH * NMAX + 255) / 256, 256>>>(BATCH * NMAX);
    k_init_edges_count<<<(BATCH * NEDGE + 255) / 256, 256>>>(src, dst);
    k_zero_z<<<(BATCH * 2 * NHID + 255) / 256, 256>>>();
    {
        size_t total8 = (size_t)BATCH * NMAX * FIN / 8;
        k_split_a8<<<(int)((total8 + 255) / 256), 256>>>(
            (const float4*)x, (uint4*)ahi, (uint4*)alo, total8);
    }

    // stage 1: 2048 nodes, K=256 -> h0=A, gcn=B, pool(split) -> ahi/alo (1024 nodes)
    run_stage(pA, pB, ahi, alo, whi, wlo, 2048, 1024, FIN,  W1, b1, Wp1, bp1, true,  true);
    // stage 2: 1024 nodes -> h0=A, gcn=B, pool(split) -> ahi/alo (512 nodes)
    run_stage(pA, pB, ahi, alo, whi, wlo, 1024, 512,  NHID, W2, b2, Wp2, bp2, true,  true);
    // stage 3: 512 nodes -> h0=A, gcn=B, readout only
    run_stage(pA, pB, ahi, alo, whi, wlo, 512,  256,  NHID, W3, b3, Wp3, bp3, false, false);

    k_head<<<BATCH, 256>>>(l1W, l1b, l2W, l2b, piW, pib, vW, vb, out);
}

// round 9
// speedup vs baseline: 3.7126x; 1.1804x over previous
#include <cuda_runtime.h>
#include <cuda_bf16.h>
#include <math.h>
#include <stdint.h>

#define BATCH 64
#define NMAX  2048
#define NEDGE 32768
#define FIN   256
#define NHID  512
#define RULES 128

// ---------------- scratch (device globals; no allocations) ----------------
static __device__ float g_bufA[(size_t)BATCH * NMAX * NHID];   // gemm output (relu'd h)
static __device__ float g_bufB[(size_t)BATCH * NMAX * NHID];   // pooled fp32 output
static __device__ __align__(16) __nv_bfloat16 g_ahi[(size_t)BATCH * NMAX * NHID / 2];
static __device__ __align__(16) __nv_bfloat16 g_alo[(size_t)BATCH * NMAX * NHID / 2];
static __device__ __align__(16) __nv_bfloat16 g_whi[NHID * NHID];
static __device__ __align__(16) __nv_bfloat16 g_wlo[NHID * NHID];
static __device__ int   g_cnt[BATCH * NMAX];
static __device__ int   g_rowstart[BATCH * NMAX];
static __device__ int   g_csr[BATCH * NEDGE];
static __device__ float g_s0[BATCH * NMAX];
static __device__ float g_score[BATCH * NMAX];
static __device__ int   g_perm[BATCH * NMAX];
static __device__ int   g_newidx[BATCH * NMAX];
static __device__ int   g_src[BATCH * NEDGE];
static __device__ int   g_dst[BATCH * NEDGE];
static __device__ float g_em[BATCH * NEDGE];
static __device__ float g_z[BATCH * 2 * NHID];

// ---------------- helpers ----------------
__device__ __forceinline__ uint32_t smem_u32(const void* p) {
    uint32_t a;
    asm("{ .reg .u64 t; cvta.to.shared.u64 t, %1; cvt.u32.u64 %0, t; }" : "=r"(a) : "l"(p));
    return a;
}
__device__ __forceinline__ void cp16(uint32_t saddr, const void* gptr) {
    asm volatile("cp.async.cg.shared.global [%0], [%1], 16;"
                 :: "r"(saddr), "l"(__cvta_generic_to_global(gptr)) : "memory");
}
__device__ __forceinline__ void ldsm4(uint32_t& r0, uint32_t& r1, uint32_t& r2, uint32_t& r3,
                                      uint32_t addr) {
    asm volatile("ldmatrix.sync.aligned.m8n8.x4.shared.b16 {%0,%1,%2,%3}, [%4];"
                 : "=r"(r0), "=r"(r1), "=r"(r2), "=r"(r3) : "r"(addr));
}
__device__ __forceinline__ void mma_bf16(float* c, uint32_t a0, uint32_t a1, uint32_t a2,
                                         uint32_t a3, uint32_t b0, uint32_t b1) {
    asm volatile(
        "mma.sync.aligned.m16n8k16.row.col.f32.bf16.bf16.f32 "
        "{%0,%1,%2,%3}, {%4,%5,%6,%7}, {%8,%9}, {%0,%1,%2,%3};"
        : "+f"(c[0]), "+f"(c[1]), "+f"(c[2]), "+f"(c[3])
        : "r"(a0), "r"(a1), "r"(a2), "r"(a3), "r"(b0), "r"(b1));
}
__device__ __forceinline__ uint32_t pk2(float a, float b) {
    __nv_bfloat162 t = __floats2bfloat162_rn(a, b);
    return *(uint32_t*)&t;
}

// ---------------- init ----------------
__global__ void k_zero_cnt(int total) {
    int i = blockIdx.x * blockDim.x + threadIdx.x;
    if (i < total) g_cnt[i] = 0;
}
__global__ void k_init_edges_count(const int* __restrict__ src, const int* __restrict__ dst) {
    int i = blockIdx.x * blockDim.x + threadIdx.x;
    if (i >= BATCH * NEDGE) return;
    int s = src[i], d = dst[i];
    g_src[i] = s; g_dst[i] = d; g_em[i] = 1.0f;
    int b = i / NEDGE;
    atomicAdd(&g_cnt[b * NMAX + d], 1);
}
__global__ void k_zero_z() {
    int i = blockIdx.x * blockDim.x + threadIdx.x;
    if (i < BATCH * 2 * NHID) g_z[i] = 0.0f;
}

// ---------------- fused per-batch scan + CSR fill + s0 zero ----------------
__global__ __launch_bounds__(1024) void k_scan_fill(int n) {
    __shared__ int buf[2][NMAX];
    __shared__ int cur[NMAX];
    int b = blockIdx.x, tid = threadIdx.x;
    for (int i = tid; i < n; i += 1024) buf[0][i] = g_cnt[b * n + i];
    __syncthreads();
    int s = 0;
    for (int d = 1; d < n; d <<= 1) {
        for (int i = tid; i < n; i += 1024) {
            int v = buf[s][i];
            if (i >= d) v += buf[s][i - d];
            buf[s ^ 1][i] = v;
        }
        __syncthreads();
        s ^= 1;
    }
    for (int i = tid; i < n; i += 1024) {
        int excl = (i == 0) ? 0 : buf[s][i - 1];
        g_rowstart[b * n + i] = excl;
        cur[i] = excl;
        g_s0[b * n + i] = 0.0f;     // for GEMM-epilogue scorer atomics
    }
    __syncthreads();
    for (int e = tid; e < NEDGE; e += 1024) {
        int i = b * NEDGE + e;
        if (g_em[i] != 0.0f) {
            int pos = atomicAdd(&cur[g_dst[i]], 1);
            g_csr[b * NEDGE + pos] = g_src[i];
        }
    }
}

// ---------------- input-side GCN aggregation + bf16 split ----------------
// xagg[row] = xin[row]/deg + dinv_d * sum coef_s * xin[src];  write hi/lo split.
// one block per dst row; blockDim = K/4 (64 or 128); reads fp32, writes bf16 hi/lo.
__global__ void k_gather_in(const float* __restrict__ xin,
                            __nv_bfloat16* __restrict__ hi, __nv_bfloat16* __restrict__ lo,
                            int n, int K) {
    __shared__ int   nb[128];
    __shared__ float cf[128];
    const int row = blockIdx.x;
    const int b = row / n;
    const int bn = b * n;
    const int t = threadIdx.x;
    const int TB = blockDim.x;
    const int start = g_rowstart[row];
    const int cnt = g_cnt[row];
    const float deg = (float)(cnt + 1);
    const float dinv_d = rsqrtf(deg);

    const float4 self = ((const float4*)(xin + (size_t)row * K))[t];
    float4 agg = make_float4(0.f, 0.f, 0.f, 0.f);

    for (int base = 0; base < cnt; base += TB) {
        int m = min(TB, cnt - base);
        if (t < m) {
            int s = g_csr[b * NEDGE + start + base + t];
            nb[t] = s;
            cf[t] = rsqrtf((float)(g_cnt[bn + s] + 1));
        }
        __syncthreads();
#pragma unroll 8
        for (int e = 0; e < m; e++) {
            const float c = cf[e];
            const float4 v = ((const float4*)(xin + ((size_t)bn + nb[e]) * K))[t];
            agg.x = fmaf(v.x, c, agg.x);
            agg.y = fmaf(v.y, c, agg.y);
            agg.z = fmaf(v.z, c, agg.z);
            agg.w = fmaf(v.w, c, agg.w);
        }
        __syncthreads();
    }
    float4 r;
    r.x = self.x / deg + dinv_d * agg.x;
    r.y = self.y / deg + dinv_d * agg.y;
    r.z = self.z / deg + dinv_d * agg.z;
    r.w = self.w / deg + dinv_d * agg.w;
    float lx = r.x - __bfloat162float(__float2bfloat16(r.x));
    float ly = r.y - __bfloat162float(__float2bfloat16(r.y));
    float lz = r.z - __bfloat162float(__float2bfloat16(r.z));
    float lw = r.w - __bfloat162float(__float2bfloat16(r.w));
    ((uint2*)(hi + (size_t)row * K))[t] = make_uint2(pk2(r.x, r.y), pk2(r.z, r.w));
    ((uint2*)(lo + (size_t)row * K))[t] = make_uint2(pk2(lx, ly), pk2(lz, lw));
}

// ---------------- weight split + transpose via smem tile ----------------
__global__ void k_split_w(const float* __restrict__ W, __nv_bfloat16* __restrict__ hi,
                          __nv_bfloat16* __restrict__ lo, int K) {
    __shared__ float tile[32][33];
    const int k0 = blockIdx.x * 32, n0 = blockIdx.y * 32;
    const int tx = threadIdx.x, ty = threadIdx.y;
#pragma unroll
    for (int j = 0; j < 4; j++) {
        int kr = ty + j * 8;
        tile[kr][tx] = W[(size_t)(k0 + kr) * 512 + n0 + tx];
    }
    __syncthreads();
#pragma unroll
    for (int j = 0; j < 4; j++) {
        int nr = ty + j * 8;
        float v = tile[tx][nr];
        __nv_bfloat16 h = __float2bfloat16(v);
        size_t o = (size_t)(n0 + nr) * K + k0 + tx;
        hi[o] = h;
        lo[o] = __float2bfloat16(v - __bfloat162float(h));
    }
}

// ---------------- split-bf16 tensor GEMM + fused bias/relu/scorer epilogue ----------------
// gout[M,512] = relu(Xagg @ W + bias);  g_s0[row] += gout[row]·Wp (partial atomics)
#define LDS_E   40
#define TILE_A  (128 * LDS_E * 2)
#define TILE_BS (256 * LDS_E * 2)
#define STAGE_B (2 * TILE_A + 2 * TILE_BS)
#define GEMM_SMEM (3 * STAGE_B)
__global__ __launch_bounds__(512, 1) void k_gemm_mma(
    const __nv_bfloat16* __restrict__ Ahi, const __nv_bfloat16* __restrict__ Alo,
    const __nv_bfloat16* __restrict__ Bhi, const __nv_bfloat16* __restrict__ Blo,
    float* __restrict__ C, const float* __restrict__ bias, const float* __restrict__ Wp,
    int M, int K)
{
    extern __shared__ __align__(128) char smem[];
    const uint32_t sb = smem_u32(smem);
    const int tid = threadIdx.x;
    const int wid = tid >> 5;
    const int lane = tid & 31;
    const int warp_m = wid & 3;
    const int warp_n = wid >> 2;
    const int rowBase = blockIdx.y * 128;
    const int colBase = blockIdx.x * 256;

    const int g = lane >> 3;
    const int a_m = lane & 15;
    const int a_k = (lane >> 4) << 3;
    const int b_n = lane - ((g == 0) ? 0 : (g == 3) ? 16 : 8);
    const int b_k = (g & 1) << 3;

    uint32_t aoff[2], boff[4];
#pragma unroll
    for (int mt = 0; mt < 2; mt++)
        aoff[mt] = ((warp_m * 32 + mt * 16 + a_m) * LDS_E + a_k) * 2;
#pragma unroll
    for (int ng = 0; ng < 4; ng++)
        boff[ng] = ((warp_n * 64 + ng * 16 + b_n) * LDS_E + b_k) * 2;

    float acc[2][8][4];
#pragma unroll
    for (int mt = 0; mt < 2; mt++)
#pragma unroll
        for (int nf = 0; nf < 8; nf++)
#pragma unroll
            for (int e = 0; e < 4; e++) acc[mt][nf][e] = 0.0f;

    const int nch = K >> 5;

    auto load_stage = [&](int t) {
        const uint32_t base = sb + (t % 3) * STAGE_B;
        const int kc0 = t << 5;
        {
            int r = tid >> 2, blk = tid & 3;
            uint32_t so = r * (LDS_E * 2) + blk * 16;
            size_t ga = (size_t)(rowBase + r) * K + kc0 + blk * 8;
            cp16(base + so,          Ahi + ga);
            cp16(base + TILE_A + so, Alo + ga);
        }
#pragma unroll
        for (int part = 0; part < 2; part++) {
            int idx = tid + part * 512;
            int r = idx >> 2, blk = idx & 3;
            uint32_t so = r * (LDS_E * 2) + blk * 16;
            size_t gb = (size_t)(colBase + r) * K + kc0 + blk * 8;
            cp16(base + 2 * TILE_A + so,           Bhi + gb);
            cp16(base + 2 * TILE_A + TILE_BS + so, Blo + gb);
        }
        asm volatile("cp.async.commit_group;" ::: "memory");
    };

    load_stage(0);
    if (nch > 1) load_stage(1);
    for (int t = 0; t < nch; t++) {
        if (t + 2 < nch) {
            load_stage(t + 2);
            asm volatile("cp.async.wait_group 2;" ::: "memory");
        } else if (t + 1 < nch) {
            asm volatile("cp.async.wait_group 1;" ::: "memory");
        } else {
            asm volatile("cp.async.wait_group 0;" ::: "memory");
        }
        __syncthreads();
        const uint32_t base = sb + (t % 3) * STAGE_B;
        const uint32_t bbase = base + 2 * TILE_A;
#pragma unroll
        for (int kk = 0; kk < 2; kk++) {
            const uint32_t ko = kk * 32;
            uint32_t ah[2][4], al[2][4];
#pragma unroll
            for (int mt = 0; mt < 2; mt++) {
                ldsm4(ah[mt][0], ah[mt][1], ah[mt][2], ah[mt][3], base + aoff[mt] + ko);
                ldsm4(al[mt][0], al[mt][1], al[mt][2], al[mt][3], base + TILE_A + aoff[mt] + ko);
            }
#pragma unroll
            for (int half = 0; half < 2; half++) {
                uint32_t bh[4][2], bl[4][2];
#pragma unroll
                for (int gg = 0; gg < 2; gg++) {
                    int ng = half * 2 + gg;
                    uint32_t r0, r1, r2, r3;
                    ldsm4(r0, r1, r2, r3, bbase + boff[ng] + ko);
                    bh[gg * 2][0] = r0; bh[gg * 2][1] = r1;
                    bh[gg * 2 + 1][0] = r2; bh[gg * 2 + 1][1] = r3;
                    ldsm4(r0, r1, r2, r3, bbase + TILE_BS + boff[ng] + ko);
                    bl[gg * 2][0] = r0; bl[gg * 2][1] = r1;
                    bl[gg * 2 + 1][0] = r2; bl[gg * 2 + 1][1] = r3;
                }
#pragma unroll
                for (int mt = 0; mt < 2; mt++)
#pragma unroll
                    for (int q = 0; q < 4; q++) {
                        int nf = half * 4 + q;
                        mma_bf16(acc[mt][nf], ah[mt][0], ah[mt][1], ah[mt][2], ah[mt][3],
                                 bh[q][0], bh[q][1]);
                        mma_bf16(acc[mt][nf], ah[mt][0], ah[mt][1], ah[mt][2], ah[mt][3],
                                 bl[q][0], bl[q][1]);
                        mma_bf16(acc[mt][nf], al[mt][0], al[mt][1], al[mt][2], al[mt][3],
                                 bh[q][0], bh[q][1]);
                    }
            }
        }
        __syncthreads();
    }

    // fused epilogue: bias + relu + store + partial scorer dot
    float sdot[2][2] = {{0.f, 0.f}, {0.f, 0.f}};
#pragma unroll
    for (int mt = 0; mt < 2; mt++) {
        int r0 = rowBase + warp_m * 32 + mt * 16 + (lane >> 2);
        int r1 = r0 + 8;
#pragma unroll
        for (int nf = 0; nf < 8; nf++) {
            int col = colBase + warp_n * 64 + nf * 8 + (lane & 3) * 2;
            float b0 = bias[col], b1 = bias[col + 1];
            float w0 = Wp[col],   w1 = Wp[col + 1];
            float v00 = fmaxf(acc[mt][nf][0] + b0, 0.0f);
            float v01 = fmaxf(acc[mt][nf][1] + b1, 0.0f);
            float v10 = fmaxf(acc[mt][nf][2] + b0, 0.0f);
            float v11 = fmaxf(acc[mt][nf][3] + b1, 0.0f);
            *(float2*)(C + (size_t)r0 * 512 + col) = make_float2(v00, v01);
            *(float2*)(C + (size_t)r1 * 512 + col) = make_float2(v10, v11);
            sdot[mt][0] = fmaf(v00, w0, fmaf(v01, w1, sdot[mt][0]));
            sdot[mt][1] = fmaf(v10, w0, fmaf(v11, w1, sdot[mt][1]));
        }
    }
#pragma unroll
    for (int off = 1; off < 4; off <<= 1) {
#pragma unroll
        for (int mt = 0; mt < 2; mt++) {
            sdot[mt][0] += __shfl_xor_sync(0xffffffffu, sdot[mt][0], off);
            sdot[mt][1] += __shfl_xor_sync(0xffffffffu, sdot[mt][1], off);
        }
    }
    if ((lane & 3) == 0) {
#pragma unroll
        for (int mt = 0; mt < 2; mt++) {
            int r0 = rowBase + warp_m * 32 + mt * 16 + (lane >> 2);
            atomicAdd(&g_s0[r0], sdot[mt][0]);
            atomicAdd(&g_s0[r0 + 8], sdot[mt][1]);
        }
    }
}

// ---------------- score propagate ----------------
__global__ void k_score(const float* __restrict__ bp, int n) {
    int row = blockIdx.x * 8 + (threadIdx.x >> 5);
    if (row >= BATCH * n) return;
    int lane = threadIdx.x & 31;
    int b = row / n, bn = b * n;
    int start = g_rowstart[row];
    int cnt = g_cnt[row];
    float sum = 0.0f;
    for (int e = lane; e < cnt; e += 32) {
        int s = g_csr[b * NEDGE + start + e];
        sum += g_s0[bn + s] * rsqrtf((float)(g_cnt[bn + s] + 1));
    }
#pragma unroll
    for (int o = 16; o > 0; o >>= 1) sum += __shfl_down_sync(0xffffffffu, sum, o);
    if (lane == 0) {
        float deg = (float)(cnt + 1);
        g_score[row] = g_s0[row] / deg + rsqrtf(deg) * sum + bp[0];
    }
}

// ---------------- top-k: per-batch bitonic sort ----------------
__global__ void k_topk(int n, int k) {
    extern __shared__ char sm[];
    float* sv = (float*)sm;
    int* si = (int*)(sv + n);
    int b = blockIdx.x, tid = threadIdx.x;
    for (int i = tid; i < n; i += blockDim.x) { sv[i] = g_score[b * n + i]; si[i] = i; }
    __syncthreads();
    for (int ksz = 2; ksz <= n; ksz <<= 1) {
        for (int j = ksz >> 1; j > 0; j >>= 1) {
            for (int i = tid; i < n; i += blockDim.x) {
                int ixj = i ^ j;
                if (ixj > i) {
                    float v1 = sv[i], v2 = sv[ixj];
                    int i1 = si[i], i2 = si[ixj];
                    bool before = (v1 > v2) || (v1 == v2 && i1 < i2);
                    bool desc = ((i & ksz) == 0);
                    if (desc ? !before : before) {
                        sv[i] = v2; sv[ixj] = v1; si[i] = i2; si[ixj] = i1;
                    }
                }
            }
            __syncthreads();
        }
    }
    for (int i = tid; i < n; i += blockDim.x) g_newidx[b * n + i] = -1;
    __syncthreads();
    for (int t = tid; t < k; t += blockDim.x) {
        int p = si[t];
        g_perm[b * n + t] = p;
        g_newidx[b * n + p] = t;
    }
}

// ---------------- fused pool + readout (fp32 pooled out for next gather) ----------------
__global__ __launch_bounds__(128) void k_pool_readout(const float* __restrict__ h,
                                                      float* __restrict__ outp,
                                                      int n, int k) {
    __shared__ float tv[1024];
    __shared__ int   pp[1024];
    const int b = blockIdx.x, fc = blockIdx.y, t = threadIdx.x;
    for (int r = t; r < k; r += 128) {
        int p = g_perm[b * n + r];
        pp[r] = p;
        tv[r] = tanhf(g_score[b * n + p]);
    }
    __syncthreads();
    const int f = fc * 128 + t;
    float mx = -INFINITY, sm = 0.0f;
    if (outp) {
        for (int r = 0; r < k; r++) {
            float v = h[((size_t)b * n + pp[r]) * NHID + f] * tv[r];
            mx = fmaxf(mx, v);
            sm += v;
            outp[((size_t)b * k + r) * NHID + f] = v;
        }
    } else {
        for (int r = 0; r < k; r++) {
            float v = h[((size_t)b * n + pp[r]) * NHID + f] * tv[r];
            mx = fmaxf(mx, v);
            sm += v;
        }
    }
    g_z[b * 1024 + f] += mx;
    g_z[b * 1024 + 512 + f] += sm / (float)k;
}

// ---------------- edge relabel + count for next stage ----------------
__global__ void k_edge_update_count(int n, int k) {
    int i = blockIdx.x * blockDim.x + threadIdx.x;
    if (i >= BATCH * NEDGE) return;
    int b = i / NEDGE;
    if (g_em[i] != 0.0f) {
        int ns = g_newidx[b * n + g_src[i]];
        int nd = g_newidx[b * n + g_dst[i]];
        if (ns >= 0 && nd >= 0) {
            g_src[i] = ns; g_dst[i] = nd;
            atomicAdd(&g_cnt[b * k + nd], 1);
        } else { g_em[i] = 0.0f; g_src[i] = 0; g_dst[i] = 0; }
    } else { g_src[i] = 0; g_dst[i] = 0; }
}

// ---------------- head ----------------
__global__ void k_head(const float* __restrict__ l1W, const float* __restrict__ l1b,
                       const float* __restrict__ l2W, const float* __restrict__ l2b,
                       const float* __restrict__ piW, const float* __restrict__ pib,
                       const float* __restrict__ vW, const float* __restrict__ vb,
                       float* __restrict__ out) {
    __shared__ float zz[1024];
    __shared__ float z1[512];
    __shared__ float z2[256];
    __shared__ float lg[128];
    __shared__ float stats[2];
    int b = blockIdx.x, tid = threadIdx.x;
    for (int i = tid; i < 1024; i += 256) zz[i] = g_z[b * 1024 + i];
    __syncthreads();
    for (int j = tid; j < 512; j += 256) {
        float a = l1b[j];
        for (int i = 0; i < 1024; i++) a = fmaf(zz[i], l1W[i * 512 + j], a);
        z1[j] = fmaxf(a, 0.0f);
    }
    __syncthreads();
    {
        int j = tid;
        float a = l2b[j];
        for (int i = 0; i < 512; i++) a = fmaf(z1[i], l2W[i * 256 + j], a);
        z2[j] = fmaxf(a, 0.0f);
    }
    __syncthreads();
    if (tid < 128) {
        float a = pib[tid];
        for (int i = 0; i < 256; i++) a = fmaf(z2[i], piW[i * 128 + tid], a);
        lg[tid] = a;
    } else if (tid == 128) {
        float a = vb[0];
        for (int i = 0; i < 256; i++) a = fmaf(z2[i], vW[i], a);
        out[BATCH * RULES + b] = fmaxf(a, 0.0f);
    }
    __syncthreads();
    if (tid == 0) {
        float mx = -INFINITY;
        for (int i = 0; i < 128; i++) mx = fmaxf(mx, lg[i]);
        float s = 0.0f;
        for (int i = 0; i < 128; i++) s += expf(lg[i] - mx);
        stats[0] = mx;
        stats[1] = logf(s);
    }
    __syncthreads();
    if (tid < 128) out[b * RULES + tid] = lg[tid] - stats[0] - stats[1];
}

// ---------------- host orchestration ----------------
static void run_stage(const float* xin, float* gout, float* pooled,
                      __nv_bfloat16* ahi, __nv_bfloat16* alo,
                      __nv_bfloat16* whi, __nv_bfloat16* wlo,
                      int n, int k, int K,
                      const float* W, const float* bias,
                      const float* Wp, const float* bp, bool relabel, bool first) {
    const int EB = BATCH * NEDGE;
    k_scan_fill<<<BATCH, 1024>>>(n);
    k_gather_in<<<BATCH * n, K / 4>>>(xin, ahi, alo, n, K);
    k_split_w<<<dim3(K / 32, 16), dim3(32, 8)>>>(W, whi, wlo, K);
    k_gemm_mma<<<dim3(2, (BATCH * n) / 128), 512, GEMM_SMEM>>>(ahi, alo, whi, wlo, gout,
                                                               bias, Wp, BATCH * n, K);
    if (first) k_zero_z<<<(BATCH * 2 * NHID + 255) / 256, 256>>>();
    k_score<<<(BATCH * n) / 8, 256>>>(bp, n);
    k_topk<<<BATCH, 1024, n * 8>>>(n, k);
    k_pool_readout<<<dim3(BATCH, 4), 128>>>(gout, pooled, n, k);
    if (relabel) {
        k_zero_cnt<<<(BATCH * k + 255) / 256, 256>>>(BATCH * k);
        k_edge_update_count<<<(EB + 255) / 256, 256>>>(n, k);
    }
}

extern "C" void kernel_launch(void* const* d_in, const int* in_sizes, int n_in,
                              void* d_out, int out_size) {
    const float* x    = (const float*)d_in[0];
    const int*   src  = (const int*)d_in[1];
    const int*   dst  = (const int*)d_in[2];
    const float* W1   = (const float*)d_in[3];
    const float* b1   = (const float*)d_in[4];
    const float* Wp1  = (const float*)d_in[5];
    const float* bp1  = (const float*)d_in[6];
    const float* W2   = (const float*)d_in[7];
    const float* b2   = (const float*)d_in[8];
    const float* Wp2  = (const float*)d_in[9];
    const float* bp2  = (const float*)d_in[10];
    const float* W3   = (const float*)d_in[11];
    const float* b3   = (const float*)d_in[12];
    const float* Wp3  = (const float*)d_in[13];
    const float* bp3  = (const float*)d_in[14];
    const float* l1W  = (const float*)d_in[15];
    const float* l1b  = (const float*)d_in[16];
    const float* l2W  = (const float*)d_in[17];
    const float* l2b  = (const float*)d_in[18];
    const float* piW  = (const float*)d_in[19];
    const float* pib  = (const float*)d_in[20];
    const float* vW   = (const float*)d_in[21];
    const float* vb   = (const float*)d_in[22];
    float* out = (float*)d_out;

    float *pA = nullptr, *pB = nullptr;
    __nv_bfloat16 *ahi = nullptr, *alo = nullptr, *whi = nullptr, *wlo = nullptr;
    cudaGetSymbolAddress((void**)&pA, g_bufA);
    cudaGetSymbolAddress((void**)&pB, g_bufB);
    cudaGetSymbolAddress((void**)&ahi, g_ahi);
    cudaGetSymbolAddress((void**)&alo, g_alo);
    cudaGetSymbolAddress((void**)&whi, g_whi);
    cudaGetSymbolAddress((void**)&wlo, g_wlo);

    cudaFuncSetAttribute(k_gemm_mma, cudaFuncAttributeMaxDynamicSharedMemorySize, GEMM_SMEM);

    k_zero_cnt<<<(BATCH * NMAX + 255) / 256, 256>>>(BATCH * NMAX);
    k_init_edges_count<<<(BATCH * NEDGE + 255) / 256, 256>>>(src, dst);

    // stage 1: gather on 256-wide input -> xagg split; GEMM (fused bias/relu/scorer) -> pA;
    //          pool -> pB (fp32, 1024 nodes)
    run_stage(x,  pA, pB, ahi, alo, whi, wlo, 2048, 1024, FIN,  W1, b1, Wp1, bp1, true,  true);
    // stage 2: gather on pB (512-wide) -> split; GEMM -> pA; pool -> pB (512 nodes)
    run_stage(pB, pA, pB, ahi, alo, whi, wlo, 1024, 512,  NHID, W2, b2, Wp2, bp2, true,  false);
    // stage 3: gather on pB -> split; GEMM -> pA; readout only
    run_stage(pB, pA, nullptr, ahi, alo, whi, wlo, 512, 256, NHID, W3, b3, Wp3, bp3, false, false);

    k_head<<<BATCH, 256>>>(l1W, l1b, l2W, l2b, piW, pib, vW, vb, out);
}

// round 11
// speedup vs baseline: 3.9789x; 1.0717x over previous
#include <cuda_runtime.h>
#include <cuda_bf16.h>
#include <math.h>
#include <stdint.h>

#define BATCH 64
#define NMAX  2048
#define NEDGE 32768
#define FIN   256
#define NHID  512
#define RULES 128

// ---------------- scratch (device globals; no allocations) ----------------
static __device__ float g_bufA[(size_t)BATCH * NMAX * NHID];   // gemm outputs (ping)
static __device__ float g_bufB[(size_t)BATCH * NMAX * NHID];   // gemm outputs (pong)
static __device__ __align__(16) __nv_bfloat16 g_ahi[(size_t)BATCH * NMAX * NHID / 2];
static __device__ __align__(16) __nv_bfloat16 g_alo[(size_t)BATCH * NMAX * NHID / 2];
static __device__ __align__(16) __nv_bfloat16 g_whi[NHID * NHID];
static __device__ __align__(16) __nv_bfloat16 g_wlo[NHID * NHID];
static __device__ int   g_cnt[BATCH * NMAX];
static __device__ int   g_rowstart[BATCH * NMAX];
static __device__ int   g_csr[BATCH * NEDGE];
static __device__ float g_s0[BATCH * NMAX];
static __device__ float g_score[BATCH * NMAX];
static __device__ float g_tv[BATCH * NMAX];
static __device__ int   g_perm[BATCH * NMAX];
static __device__ int   g_newidx[BATCH * NMAX];
static __device__ int   g_src[BATCH * NEDGE];
static __device__ int   g_dst[BATCH * NEDGE];
static __device__ float g_em[BATCH * NEDGE];
static __device__ float g_z[BATCH * 2 * NHID];

// ---------------- helpers ----------------
__device__ __forceinline__ uint32_t smem_u32(const void* p) {
    uint32_t a;
    asm("{ .reg .u64 t; cvta.to.shared.u64 t, %1; cvt.u32.u64 %0, t; }" : "=r"(a) : "l"(p));
    return a;
}
__device__ __forceinline__ void cp16(uint32_t saddr, const void* gptr) {
    asm volatile("cp.async.cg.shared.global [%0], [%1], 16;"
                 :: "r"(saddr), "l"(__cvta_generic_to_global(gptr)) : "memory");
}
__device__ __forceinline__ void ldsm4(uint32_t& r0, uint32_t& r1, uint32_t& r2, uint32_t& r3,
                                      uint32_t addr) {
    asm volatile("ldmatrix.sync.aligned.m8n8.x4.shared.b16 {%0,%1,%2,%3}, [%4];"
                 : "=r"(r0), "=r"(r1), "=r"(r2), "=r"(r3) : "r"(addr));
}
__device__ __forceinline__ void mma_bf16(float* c, uint32_t a0, uint32_t a1, uint32_t a2,
                                         uint32_t a3, uint32_t b0, uint32_t b1) {
    asm volatile(
        "mma.sync.aligned.m16n8k16.row.col.f32.bf16.bf16.f32 "
        "{%0,%1,%2,%3}, {%4,%5,%6,%7}, {%8,%9}, {%0,%1,%2,%3};"
        : "+f"(c[0]), "+f"(c[1]), "+f"(c[2]), "+f"(c[3])
        : "r"(a0), "r"(a1), "r"(a2), "r"(a3), "r"(b0), "r"(b1));
}
__device__ __forceinline__ uint32_t pk2(float a, float b) {
    __nv_bfloat162 t = __floats2bfloat162_rn(a, b);
    return *(uint32_t*)&t;
}

// ---------------- init ----------------
__global__ void k_zero_cnt(int total) {
    int i = blockIdx.x * blockDim.x + threadIdx.x;
    if (i < total) g_cnt[i] = 0;
}
__global__ void k_init_edges_count(const int* __restrict__ src, const int* __restrict__ dst) {
    int i = blockIdx.x * blockDim.x + threadIdx.x;
    if (i >= BATCH * NEDGE) return;
    int s = src[i], d = dst[i];
    g_src[i] = s; g_dst[i] = d; g_em[i] = 1.0f;
    int b = i / NEDGE;
    atomicAdd(&g_cnt[b * NMAX + d], 1);
}
__global__ void k_zero_z() {
    int i = blockIdx.x * blockDim.x + threadIdx.x;
    if (i < BATCH * 2 * NHID) g_z[i] = 0.0f;
}

// ---------------- fused per-batch scan + CSR fill + s0 zero ----------------
__global__ __launch_bounds__(1024) void k_scan_fill(int n) {
    __shared__ int buf[2][NMAX];
    __shared__ int cur[NMAX];
    int b = blockIdx.x, tid = threadIdx.x;
    for (int i = tid; i < n; i += 1024) buf[0][i] = g_cnt[b * n + i];
    __syncthreads();
    int s = 0;
    for (int d = 1; d < n; d <<= 1) {
        for (int i = tid; i < n; i += 1024) {
            int v = buf[s][i];
            if (i >= d) v += buf[s][i - d];
            buf[s ^ 1][i] = v;
        }
        __syncthreads();
        s ^= 1;
    }
    for (int i = tid; i < n; i += 1024) {
        int excl = (i == 0) ? 0 : buf[s][i - 1];
        g_rowstart[b * n + i] = excl;
        cur[i] = excl;
        g_s0[b * n + i] = 0.0f;
    }
    __syncthreads();
    for (int e = tid; e < NEDGE; e += 1024) {
        int i = b * NEDGE + e;
        if (g_em[i] != 0.0f) {
            int pos = atomicAdd(&cur[g_dst[i]], 1);
            g_csr[b * NEDGE + pos] = g_src[i];
        }
    }
}

// ---------------- warp-per-row GCN aggregation + bf16 split ----------------
// VEC = K/128 float4 per lane; optional perm-indirection into previous gout.
template<int VEC, int USE_PERM>
__global__ __launch_bounds__(256) void k_gather_w(const float* __restrict__ xin,
                                                  __nv_bfloat16* __restrict__ hi,
                                                  __nv_bfloat16* __restrict__ lo,
                                                  int n, int n_old) {
    const int K = VEC * 128;
    const int gw = (blockIdx.x * 256 + threadIdx.x) >> 5;   // row in new space
    const int lane = threadIdx.x & 31;
    const int b = gw / n;
    const int r = gw - b * n;
    const int bn = b * n;
    const int start = g_rowstart[gw];
    const int cnt = g_cnt[gw];
    const float deg = (float)(cnt + 1);
    const float dinv = rsqrtf(deg);

    int srow; float sscale;
    if (USE_PERM) {
        int p = g_perm[b * n_old + r];
        srow = b * n_old + p;
        sscale = g_tv[srow] / deg;
    } else {
        srow = bn + r;
        sscale = 1.0f / deg;
    }

    float4 acc[VEC];
#pragma unroll
    for (int j = 0; j < VEC; j++) acc[j] = make_float4(0.f, 0.f, 0.f, 0.f);

    for (int base = 0; base < cnt; base += 32) {
        int m = min(32, cnt - base);
        int off = 0; float c = 0.0f;
        if (lane < m) {
            int s = g_csr[b * NEDGE + start + base + lane];
            c = rsqrtf((float)(g_cnt[bn + s] + 1));
            int orow;
            if (USE_PERM) {
                orow = b * n_old + g_perm[b * n_old + s];
                c *= g_tv[orow];
            } else {
                orow = bn + s;
            }
            off = orow * K;   // float-element offset (< 2^27)
        }
#pragma unroll 4
        for (int e = 0; e < m; e++) {
            int o = __shfl_sync(0xffffffffu, off, e);
            float cc = __shfl_sync(0xffffffffu, c, e);
            const float4* p = (const float4*)(xin + o);
#pragma unroll
            for (int j = 0; j < VEC; j++) {
                float4 v = p[lane + j * 32];
                acc[j].x = fmaf(v.x, cc, acc[j].x);
                acc[j].y = fmaf(v.y, cc, acc[j].y);
                acc[j].z = fmaf(v.z, cc, acc[j].z);
                acc[j].w = fmaf(v.w, cc, acc[j].w);
            }
        }
    }
    const float4* selfp = (const float4*)(xin + (size_t)srow * K);
    uint2* hp = (uint2*)(hi + (size_t)gw * K);
    uint2* lp = (uint2*)(lo + (size_t)gw * K);
#pragma unroll
    for (int j = 0; j < VEC; j++) {
        float4 sv = selfp[lane + j * 32];
        float rx = sv.x * sscale + dinv * acc[j].x;
        float ry = sv.y * sscale + dinv * acc[j].y;
        float rz = sv.z * sscale + dinv * acc[j].z;
        float rw = sv.w * sscale + dinv * acc[j].w;
        float lx = rx - __bfloat162float(__float2bfloat16(rx));
        float ly = ry - __bfloat162float(__float2bfloat16(ry));
        float lz = rz - __bfloat162float(__float2bfloat16(rz));
        float lw = rw - __bfloat162float(__float2bfloat16(rw));
        hp[lane + j * 32] = make_uint2(pk2(rx, ry), pk2(rz, rw));
        lp[lane + j * 32] = make_uint2(pk2(lx, ly), pk2(lz, lw));
    }
}

// ---------------- weight split + transpose via smem tile ----------------
__global__ void k_split_w(const float* __restrict__ W, __nv_bfloat16* __restrict__ hi,
                          __nv_bfloat16* __restrict__ lo, int K) {
    __shared__ float tile[32][33];
    const int k0 = blockIdx.x * 32, n0 = blockIdx.y * 32;
    const int tx = threadIdx.x, ty = threadIdx.y;
#pragma unroll
    for (int j = 0; j < 4; j++) {
        int kr = ty + j * 8;
        tile[kr][tx] = W[(size_t)(k0 + kr) * 512 + n0 + tx];
    }
    __syncthreads();
#pragma unroll
    for (int j = 0; j < 4; j++) {
        int nr = ty + j * 8;
        float v = tile[tx][nr];
        __nv_bfloat16 h = __float2bfloat16(v);
        size_t o = (size_t)(n0 + nr) * K + k0 + tx;
        hi[o] = h;
        lo[o] = __float2bfloat16(v - __bfloat162float(h));
    }
}

// ---------------- split-bf16 tensor GEMM + fused bias/relu/scorer epilogue ----------------
#define LDS_E   40
#define TILE_A  (128 * LDS_E * 2)
#define TILE_BS (256 * LDS_E * 2)
#define STAGE_B (2 * TILE_A + 2 * TILE_BS)
#define GEMM_SMEM (3 * STAGE_B)
__global__ __launch_bounds__(512, 1) void k_gemm_mma(
    const __nv_bfloat16* __restrict__ Ahi, const __nv_bfloat16* __restrict__ Alo,
    const __nv_bfloat16* __restrict__ Bhi, const __nv_bfloat16* __restrict__ Blo,
    float* __restrict__ C, const float* __restrict__ bias, const float* __restrict__ Wp,
    int M, int K)
{
    extern __shared__ __align__(128) char smem[];
    const uint32_t sb = smem_u32(smem);
    const int tid = threadIdx.x;
    const int wid = tid >> 5;
    const int lane = tid & 31;
    const int warp_m = wid & 3;
    const int warp_n = wid >> 2;
    const int rowBase = blockIdx.y * 128;
    const int colBase = blockIdx.x * 256;

    const int g = lane >> 3;
    const int a_m = lane & 15;
    const int a_k = (lane >> 4) << 3;
    const int b_n = lane - ((g == 0) ? 0 : (g == 3) ? 16 : 8);
    const int b_k = (g & 1) << 3;

    uint32_t aoff[2], boff[4];
#pragma unroll
    for (int mt = 0; mt < 2; mt++)
        aoff[mt] = ((warp_m * 32 + mt * 16 + a_m) * LDS_E + a_k) * 2;
#pragma unroll
    for (int ng = 0; ng < 4; ng++)
        boff[ng] = ((warp_n * 64 + ng * 16 + b_n) * LDS_E + b_k) * 2;

    float acc[2][8][4];
#pragma unroll
    for (int mt = 0; mt < 2; mt++)
#pragma unroll
        for (int nf = 0; nf < 8; nf++)
#pragma unroll
            for (int e = 0; e < 4; e++) acc[mt][nf][e] = 0.0f;

    const int nch = K >> 5;

    auto load_stage = [&](int t) {
        const uint32_t base = sb + (t % 3) * STAGE_B;
        const int kc0 = t << 5;
        {
            int r = tid >> 2, blk = tid & 3;
            uint32_t so = r * (LDS_E * 2) + blk * 16;
            size_t ga = (size_t)(rowBase + r) * K + kc0 + blk * 8;
            cp16(base + so,          Ahi + ga);
            cp16(base + TILE_A + so, Alo + ga);
        }
#pragma unroll
        for (int part = 0; part < 2; part++) {
            int idx = tid + part * 512;
            int r = idx >> 2, blk = idx & 3;
            uint32_t so = r * (LDS_E * 2) + blk * 16;
            size_t gb = (size_t)(colBase + r) * K + kc0 + blk * 8;
            cp16(base + 2 * TILE_A + so,           Bhi + gb);
            cp16(base + 2 * TILE_A + TILE_BS + so, Blo + gb);
        }
        asm volatile("cp.async.commit_group;" ::: "memory");
    };

    load_stage(0);
    if (nch > 1) load_stage(1);
    for (int t = 0; t < nch; t++) {
        if (t + 2 < nch) {
            load_stage(t + 2);
            asm volatile("cp.async.wait_group 2;" ::: "memory");
        } else if (t + 1 < nch) {
            asm volatile("cp.async.wait_group 1;" ::: "memory");
        } else {
            asm volatile("cp.async.wait_group 0;" ::: "memory");
        }
        __syncthreads();
        const uint32_t base = sb + (t % 3) * STAGE_B;
        const uint32_t bbase = base + 2 * TILE_A;
#pragma unroll
        for (int kk = 0; kk < 2; kk++) {
            const uint32_t ko = kk * 32;
            uint32_t ah[2][4], al[2][4];
#pragma unroll
            for (int mt = 0; mt < 2; mt++) {
                ldsm4(ah[mt][0], ah[mt][1], ah[mt][2], ah[mt][3], base + aoff[mt] + ko);
                ldsm4(al[mt][0], al[mt][1], al[mt][2], al[mt][3], base + TILE_A + aoff[mt] + ko);
            }
#pragma unroll
            for (int half = 0; half < 2; half++) {
                uint32_t bh[4][2], bl[4][2];
#pragma unroll
                for (int gg = 0; gg < 2; gg++) {
                    int ng = half * 2 + gg;
                    uint32_t r0, r1, r2, r3;
                    ldsm4(r0, r1, r2, r3, bbase + boff[ng] + ko);
                    bh[gg * 2][0] = r0; bh[gg * 2][1] = r1;
                    bh[gg * 2 + 1][0] = r2; bh[gg * 2 + 1][1] = r3;
                    ldsm4(r0, r1, r2, r3, bbase + TILE_BS + boff[ng] + ko);
                    bl[gg * 2][0] = r0; bl[gg * 2][1] = r1;
                    bl[gg * 2 + 1][0] = r2; bl[gg * 2 + 1][1] = r3;
                }
#pragma unroll
                for (int mt = 0; mt < 2; mt++)
#pragma unroll
                    for (int q = 0; q < 4; q++) {
                        int nf = half * 4 + q;
                        mma_bf16(acc[mt][nf], ah[mt][0], ah[mt][1], ah[mt][2], ah[mt][3],
                                 bh[q][0], bh[q][1]);
                        mma_bf16(acc[mt][nf], ah[mt][0], ah[mt][1], ah[mt][2], ah[mt][3],
                                 bl[q][0], bl[q][1]);
                        mma_bf16(acc[mt][nf], al[mt][0], al[mt][1], al[mt][2], al[mt][3],
                                 bh[q][0], bh[q][1]);
                    }
            }
        }
        __syncthreads();
    }

    float sdot[2][2] = {{0.f, 0.f}, {0.f, 0.f}};
#pragma unroll
    for (int mt = 0; mt < 2; mt++) {
        int r0 = rowBase + warp_m * 32 + mt * 16 + (lane >> 2);
        int r1 = r0 + 8;
#pragma unroll
        for (int nf = 0; nf < 8; nf++) {
            int col = colBase + warp_n * 64 + nf * 8 + (lane & 3) * 2;
            float b0 = bias[col], b1 = bias[col + 1];
            float w0 = Wp[col],   w1 = Wp[col + 1];
            float v00 = fmaxf(acc[mt][nf][0] + b0, 0.0f);
            float v01 = fmaxf(acc[mt][nf][1] + b1, 0.0f);
            float v10 = fmaxf(acc[mt][nf][2] + b0, 0.0f);
            float v11 = fmaxf(acc[mt][nf][3] + b1, 0.0f);
            *(float2*)(C + (size_t)r0 * 512 + col) = make_float2(v00, v01);
            *(float2*)(C + (size_t)r1 * 512 + col) = make_float2(v10, v11);
            sdot[mt][0] = fmaf(v00, w0, fmaf(v01, w1, sdot[mt][0]));
            sdot[mt][1] = fmaf(v10, w0, fmaf(v11, w1, sdot[mt][1]));
        }
    }
#pragma unroll
    for (int off = 1; off < 4; off <<= 1) {
#pragma unroll
        for (int mt = 0; mt < 2; mt++) {
            sdot[mt][0] += __shfl_xor_sync(0xffffffffu, sdot[mt][0], off);
            sdot[mt][1] += __shfl_xor_sync(0xffffffffu, sdot[mt][1], off);
        }
    }
    if ((lane & 3) == 0) {
#pragma unroll
        for (int mt = 0; mt < 2; mt++) {
            int r0 = rowBase + warp_m * 32 + mt * 16 + (lane >> 2);
            atomicAdd(&g_s0[r0], sdot[mt][0]);
            atomicAdd(&g_s0[r0 + 8], sdot[mt][1]);
        }
    }
}

// ---------------- score propagate ----------------
__global__ void k_score(const float* __restrict__ bp, int n) {
    int row = blockIdx.x * 8 + (threadIdx.x >> 5);
    if (row >= BATCH * n) return;
    int lane = threadIdx.x & 31;
    int b = row / n, bn = b * n;
    int start = g_rowstart[row];
    int cnt = g_cnt[row];
    float sum = 0.0f;
    for (int e = lane; e < cnt; e += 32) {
        int s = g_csr[b * NEDGE + start + e];
        sum += g_s0[bn + s] * rsqrtf((float)(g_cnt[bn + s] + 1));
    }
#pragma unroll
    for (int o = 16; o > 0; o >>= 1) sum += __shfl_down_sync(0xffffffffu, sum, o);
    if (lane == 0) {
        float deg = (float)(cnt + 1);
        g_score[row] = g_s0[row] / deg + rsqrtf(deg) * sum + bp[0];
    }
}

// ---------------- top-k: per-batch bitonic sort (+ tv store) ----------------
__global__ void k_topk(int n, int k) {
    extern __shared__ char sm[];
    float* sv = (float*)sm;
    int* si = (int*)(sv + n);
    int b = blockIdx.x, tid = threadIdx.x;
    for (int i = tid; i < n; i += blockDim.x) { sv[i] = g_score[b * n + i]; si[i] = i; }
    __syncthreads();
    for (int ksz = 2; ksz <= n; ksz <<= 1) {
        for (int j = ksz >> 1; j > 0; j >>= 1) {
            for (int i = tid; i < n; i += blockDim.x) {
                int ixj = i ^ j;
                if (ixj > i) {
                    float v1 = sv[i], v2 = sv[ixj];
                    int i1 = si[i], i2 = si[ixj];
                    bool before = (v1 > v2) || (v1 == v2 && i1 < i2);
                    bool desc = ((i & ksz) == 0);
                    if (desc ? !before : before) {
                        sv[i] = v2; sv[ixj] = v1; si[i] = i2; si[ixj] = i1;
                    }
                }
            }
            __syncthreads();
        }
    }
    for (int i = tid; i < n; i += blockDim.x) g_newidx[b * n + i] = -1;
    __syncthreads();
    for (int t = tid; t < k; t += blockDim.x) {
        int p = si[t];
        g_perm[b * n + t] = p;
        g_newidx[b * n + p] = t;
        g_tv[b * n + p] = tanhf(sv[t]);
    }
}

// ---------------- readout only (max/mean over selected rows) ----------------
__global__ __launch_bounds__(128) void k_pool_readout(const float* __restrict__ h,
                                                      int n, int k) {
    __shared__ float tv[1024];
    __shared__ int   pp[1024];
    const int b = blockIdx.x, fc = blockIdx.y, t = threadIdx.x;
    for (int r = t; r < k; r += 128) {
        int p = g_perm[b * n + r];
        pp[r] = p;
        tv[r] = g_tv[b * n + p];
    }
    __syncthreads();
    const int f = fc * 128 + t;
    float mx = -INFINITY, sm = 0.0f;
    for (int r = 0; r < k; r++) {
        float v = h[((size_t)b * n + pp[r]) * NHID + f] * tv[r];
        mx = fmaxf(mx, v);
        sm += v;
    }
    g_z[b * 1024 + f] += mx;
    g_z[b * 1024 + 512 + f] += sm / (float)k;
}

// ---------------- edge relabel + count for next stage ----------------
__global__ void k_edge_update_count(int n, int k) {
    int i = blockIdx.x * blockDim.x + threadIdx.x;
    if (i >= BATCH * NEDGE) return;
    int b = i / NEDGE;
    if (g_em[i] != 0.0f) {
        int ns = g_newidx[b * n + g_src[i]];
        int nd = g_newidx[b * n + g_dst[i]];
        if (ns >= 0 && nd >= 0) {
            g_src[i] = ns; g_dst[i] = nd;
            atomicAdd(&g_cnt[b * k + nd], 1);
        } else { g_em[i] = 0.0f; g_src[i] = 0; g_dst[i] = 0; }
    } else { g_src[i] = 0; g_dst[i] = 0; }
}

// ---------------- head ----------------
__global__ void k_head(const float* __restrict__ l1W, const float* __restrict__ l1b,
                       const float* __restrict__ l2W, const float* __restrict__ l2b,
                       const float* __restrict__ piW, const float* __restrict__ pib,
                       const float* __restrict__ vW, const float* __restrict__ vb,
                       float* __restrict__ out) {
    __shared__ float zz[1024];
    __shared__ float z1[512];
    __shared__ float z2[256];
    __shared__ float lg[128];
    __shared__ float stats[2];
    int b = blockIdx.x, tid = threadIdx.x;
    for (int i = tid; i < 1024; i += 256) zz[i] = g_z[b * 1024 + i];
    __syncthreads();
    for (int j = tid; j < 512; j += 256) {
        float a = l1b[j];
        for (int i = 0; i < 1024; i++) a = fmaf(zz[i], l1W[i * 512 + j], a);
        z1[j] = fmaxf(a, 0.0f);
    }
    __syncthreads();
    {
        int j = tid;
        float a = l2b[j];
        for (int i = 0; i < 512; i++) a = fmaf(z1[i], l2W[i * 256 + j], a);
        z2[j] = fmaxf(a, 0.0f);
    }
    __syncthreads();
    if (tid < 128) {
        float a = pib[tid];
        for (int i = 0; i < 256; i++) a = fmaf(z2[i], piW[i * 128 + tid], a);
        lg[tid] = a;
    } else if (tid == 128) {
        float a = vb[0];
        for (int i = 0; i < 256; i++) a = fmaf(z2[i], vW[i], a);
        out[BATCH * RULES + b] = fmaxf(a, 0.0f);
    }
    __syncthreads();
    if (tid == 0) {
        float mx = -INFINITY;
        for (int i = 0; i < 128; i++) mx = fmaxf(mx, lg[i]);
        float s = 0.0f;
        for (int i = 0; i < 128; i++) s += expf(lg[i] - mx);
        stats[0] = mx;
        stats[1] = logf(s);
    }
    __syncthreads();
    if (tid < 128) out[b * RULES + tid] = lg[tid] - stats[0] - stats[1];
}

// ---------------- host orchestration ----------------
extern "C" void kernel_launch(void* const* d_in, const int* in_sizes, int n_in,
                              void* d_out, int out_size) {
    const float* x    = (const float*)d_in[0];
    const int*   src  = (const int*)d_in[1];
    const int*   dst  = (const int*)d_in[2];
    const float* W1   = (const float*)d_in[3];
    const float* b1   = (const float*)d_in[4];
    const float* Wp1  = (const float*)d_in[5];
    const float* bp1  = (const float*)d_in[6];
    const float* W2   = (const float*)d_in[7];
    const float* b2   = (const float*)d_in[8];
    const float* Wp2  = (const float*)d_in[9];
    const float* bp2  = (const float*)d_in[10];
    const float* W3   = (const float*)d_in[11];
    const float* b3   = (const float*)d_in[12];
    const float* Wp3  = (const float*)d_in[13];
    const float* bp3  = (const float*)d_in[14];
    const float* l1W  = (const float*)d_in[15];
    const float* l1b  = (const float*)d_in[16];
    const float* l2W  = (const float*)d_in[17];
    const float* l2b  = (const float*)d_in[18];
    const float* piW  = (const float*)d_in[19];
    const float* pib  = (const float*)d_in[20];
    const float* vW   = (const float*)d_in[21];
    const float* vb   = (const float*)d_in[22];
    float* out = (float*)d_out;

    float *pA = nullptr, *pB = nullptr;
    __nv_bfloat16 *ahi = nullptr, *alo = nullptr, *whi = nullptr, *wlo = nullptr;
    cudaGetSymbolAddress((void**)&pA, g_bufA);
    cudaGetSymbolAddress((void**)&pB, g_bufB);
    cudaGetSymbolAddress((void**)&ahi, g_ahi);
    cudaGetSymbolAddress((void**)&alo, g_alo);
    cudaGetSymbolAddress((void**)&whi, g_whi);
    cudaGetSymbolAddress((void**)&wlo, g_wlo);

    cudaFuncSetAttribute(k_gemm_mma, cudaFuncAttributeMaxDynamicSharedMemorySize, GEMM_SMEM);

    const int EB = BATCH * NEDGE;

    k_zero_cnt<<<(BATCH * NMAX + 255) / 256, 256>>>(BATCH * NMAX);
    k_init_edges_count<<<(EB + 255) / 256, 256>>>(src, dst);

    // ---- stage 1: n=2048, K=256 (gather direct from x) ----
    k_scan_fill<<<BATCH, 1024>>>(2048);
    k_gather_w<2, 0><<<BATCH * 2048 / 8, 256>>>(x, ahi, alo, 2048, 2048);
    k_split_w<<<dim3(FIN / 32, 16), dim3(32, 8)>>>(W1, whi, wlo, FIN);
    k_gemm_mma<<<dim3(2, BATCH * 2048 / 128), 512, GEMM_SMEM>>>(ahi, alo, whi, wlo, pA,
                                                                b1, Wp1, BATCH * 2048, FIN);
    k_zero_z<<<(BATCH * 2 * NHID + 255) / 256, 256>>>();
    k_score<<<BATCH * 2048 / 8, 256>>>(bp1, 2048);
    k_topk<<<BATCH, 1024, 2048 * 8>>>(2048, 1024);
    k_pool_readout<<<dim3(BATCH, 4), 128>>>(pA, 2048, 1024);
    k_zero_cnt<<<(BATCH * 1024 + 255) / 256, 256>>>(BATCH * 1024);
    k_edge_update_count<<<(EB + 255) / 256, 256>>>(2048, 1024);

    // ---- stage 2: n=1024, K=512 (gather from pA via perm over n_old=2048) ----
    k_scan_fill<<<BATCH, 1024>>>(1024);
    k_gather_w<4, 1><<<BATCH * 1024 / 8, 256>>>(pA, ahi, alo, 1024, 2048);
    k_split_w<<<dim3(NHID / 32, 16), dim3(32, 8)>>>(W2, whi, wlo, NHID);
    k_gemm_mma<<<dim3(2, BATCH * 1024 / 128), 512, GEMM_SMEM>>>(ahi, alo, whi, wlo, pB,
                                                                b2, Wp2, BATCH * 1024, NHID);
    k_score<<<BATCH * 1024 / 8, 256>>>(bp2, 1024);
    k_topk<<<BATCH, 1024, 1024 * 8>>>(1024, 512);
    k_pool_readout<<<dim3(BATCH, 4), 128>>>(pB, 1024, 512);
    k_zero_cnt<<<(BATCH * 512 + 255) / 256, 256>>>(BATCH * 512);
    k_edge_update_count<<<(EB + 255) / 256, 256>>>(1024, 512);

    // ---- stage 3: n=512, K=512 (gather from pB via perm over n_old=1024) ----
    k_scan_fill<<<BATCH, 1024>>>(512);
    k_gather_w<4, 1><<<BATCH * 512 / 8, 256>>>(pB, ahi, alo, 512, 1024);
    k_split_w<<<dim3(NHID / 32, 16), dim3(32, 8)>>>(W3, whi, wlo, NHID);
    k_gemm_mma<<<dim3(2, BATCH * 512 / 128), 512, GEMM_SMEM>>>(ahi, alo, whi, wlo, pA,
                                                               b3, Wp3, BATCH * 512, NHID);
    k_score<<<BATCH * 512 / 8, 256>>>(bp3, 512);
    k_topk<<<BATCH, 1024, 512 * 8>>>(512, 256);
    k_pool_readout<<<dim3(BATCH, 4), 128>>>(pA, 512, 256);

    k_head<<<BATCH, 256>>>(l1W, l1b, l2W, l2b, piW, pib, vW, vb, out);
}